// round 1
// baseline (speedup 1.0000x reference)
#include <cuda_runtime.h>

#define B   64
#define S   512
#define V   50257
#define E   512
#define H   1024
#define OOV 12
#define OUTW (V + OOV)     // 50269
#define KX  (E + 2*H)      // 2560
#define TH  (3*H)          // 3072
#define MS  (B*S)          // 32768

// ---------------- scratch (device globals; no allocation allowed) ----------------
__device__ float g_x[B*KX];
__device__ float g_prev[B*H];
__device__ float g_gi[B*TH];
__device__ float g_gh[B*TH];
__device__ float g_scoreg[(size_t)B*V];
__device__ float g_scorec[B*S];
__device__ float g_sc[33554432];   // MS*H = 32768*1024 (134 MB)
__device__ float g_rowmax[B];
__device__ float g_rowsum[B];

typedef unsigned long long u64;

__device__ __forceinline__ u64 pack2(float x){
    u64 r; asm("mov.b64 %0, {%1, %1};" : "=l"(r) : "f"(x)); return r;
}
__device__ __forceinline__ void ffma2(u64& d, u64 a, u64 b){
    asm("fma.rn.f32x2 %0, %1, %2, %0;" : "+l"(d) : "l"(a), "l"(b));
}
__device__ __forceinline__ void unpack2(u64 v, float& lo, float& hi){
    asm("mov.b64 {%0, %1}, %2;" : "=f"(lo), "=f"(hi) : "l"(v));
}

// ---------------- prep: x = concat(embed[input_idx], weighted) ----------------
__global__ void k_prep_x(const int* __restrict__ input_idx, const float* __restrict__ embed,
                         const float* __restrict__ weighted, const int* __restrict__ order,
                         int has_order){
    int b = blockIdx.x;
    int ord = has_order ? *order : 1;
    int idx = input_idx[b];
    for (int j = threadIdx.x; j < KX; j += blockDim.x){
        float v;
        if (j < E) v = embed[(size_t)idx*E + j];
        else       v = ord ? weighted[b*(2*H) + (j - E)] : 0.f;
        g_x[b*KX + j] = v;
    }
}

// effective prev_state (order==0 path: encoded[:,-1] @ Ws^T + Ws_b)
__global__ void k_prep_state(const float* __restrict__ prev_state, const float* __restrict__ encoded,
                             const float* __restrict__ Ws_w, const float* __restrict__ Ws_b,
                             const int* __restrict__ order, int has_order){
    int i = blockIdx.x*blockDim.x + threadIdx.x;
    if (i >= B*H) return;
    int ord = has_order ? *order : 1;
    if (ord){
        g_prev[i] = prev_state[i];
    } else {
        int b = i >> 10, h = i & (H-1);
        const float* e = encoded + ((size_t)b*S + (S-1))*(2*H);
        const float* w = Ws_w + (size_t)h*(2*H);
        float s = Ws_b[h];
        for (int k = 0; k < 2*H; k++) s = fmaf(e[k], w[k], s);
        g_prev[i] = s;
    }
}

// ---------------- generic M=64 GEMM:  C[64][N] = A[64][K] @ W[N][K]^T + bias ----------------
__global__ void __launch_bounds__(256) k_gemm64(const float* __restrict__ A, const float* __restrict__ W,
                                                const float* __restrict__ bias, float* __restrict__ C,
                                                int N, int K){
    __shared__ __align__(16) float As[16][68];
    __shared__ __align__(16) float Ws[16][68];
    int n0  = blockIdx.x * 64;
    int tid = threadIdx.x;
    int tx  = tid & 15, ty = tid >> 4;           // tx -> n group (4), ty -> m group (4)
    u64 acc[4][2] = {};
    for (int k0 = 0; k0 < K; k0 += 16){
        int row = tid >> 2;
        int kk  = (tid & 3) << 2;
        float4 a4 = *(const float4*)(A + (size_t)row*K + k0 + kk);
        As[kk+0][row]=a4.x; As[kk+1][row]=a4.y; As[kk+2][row]=a4.z; As[kk+3][row]=a4.w;
        int wr = n0 + row;
        float4 w4 = make_float4(0.f,0.f,0.f,0.f);
        if (wr < N) w4 = *(const float4*)(W + (size_t)wr*K + k0 + kk);
        Ws[kk+0][row]=w4.x; Ws[kk+1][row]=w4.y; Ws[kk+2][row]=w4.z; Ws[kk+3][row]=w4.w;
        __syncthreads();
        #pragma unroll
        for (int k = 0; k < 16; k++){
            u64 w20 = *(const u64*)&Ws[k][tx*4];
            u64 w21 = *(const u64*)&Ws[k][tx*4+2];
            #pragma unroll
            for (int i = 0; i < 4; i++){
                u64 a2 = pack2(As[k][ty*4+i]);
                ffma2(acc[i][0], a2, w20);
                ffma2(acc[i][1], a2, w21);
            }
        }
        __syncthreads();
    }
    #pragma unroll
    for (int i = 0; i < 4; i++){
        int m = ty*4 + i;
        #pragma unroll
        for (int j = 0; j < 2; j++){
            float lo, hi; unpack2(acc[i][j], lo, hi);
            int n = n0 + tx*4 + 2*j;
            if (n   < N) C[(size_t)m*N + n]   = lo + bias[n];
            if (n+1 < N) C[(size_t)m*N + n+1] = hi + bias[n+1];
        }
    }
}

// ---------------- GRU combine ----------------
__global__ void k_combine(float* __restrict__ out_state){
    int i = blockIdx.x*blockDim.x + threadIdx.x;
    if (i >= B*H) return;
    int b = i >> 10, h = i & (H-1);
    const float* gi = g_gi + b*TH;
    const float* gh = g_gh + b*TH;
    float r = 1.f/(1.f + expf(-(gi[h]        + gh[h])));
    float z = 1.f/(1.f + expf(-(gi[H + h]    + gh[H + h])));
    float n = tanhf(gi[2*H + h] + r*gh[2*H + h]);
    out_state[i] = (1.f - z)*n + z*g_prev[i];
}

// ---------------- big GEMM: sc = tanh(encoded[32768][2048] @ Wc[1024][2048]^T + b) ----------------
__global__ void __launch_bounds__(256) k_gemm_sc(const float* __restrict__ A, const float* __restrict__ W,
                                                 const float* __restrict__ bias){
    __shared__ __align__(16) float As[16][132];
    __shared__ __align__(16) float Ws[16][68];
    const int K = 2*H;                      // 2048
    int m0  = blockIdx.y * 128;
    int n0  = blockIdx.x * 64;
    int tid = threadIdx.x;
    int tx  = tid & 15, ty = tid >> 4;      // tx -> 4 n, ty -> 8 m
    u64 acc[8][2] = {};
    for (int k0 = 0; k0 < K; k0 += 16){
        #pragma unroll
        for (int v = 0; v < 2; v++){
            int idx = tid + v*256;
            int row = idx >> 2;
            int kk  = (idx & 3) << 2;
            float4 a4 = *(const float4*)(A + (size_t)(m0+row)*K + k0 + kk);
            As[kk+0][row]=a4.x; As[kk+1][row]=a4.y; As[kk+2][row]=a4.z; As[kk+3][row]=a4.w;
        }
        {
            int row = tid >> 2;
            int kk  = (tid & 3) << 2;
            float4 w4 = *(const float4*)(W + (size_t)(n0+row)*K + k0 + kk);
            Ws[kk+0][row]=w4.x; Ws[kk+1][row]=w4.y; Ws[kk+2][row]=w4.z; Ws[kk+3][row]=w4.w;
        }
        __syncthreads();
        #pragma unroll
        for (int k = 0; k < 16; k++){
            u64 w20 = *(const u64*)&Ws[k][tx*4];
            u64 w21 = *(const u64*)&Ws[k][tx*4+2];
            #pragma unroll
            for (int i = 0; i < 8; i++){
                u64 a2 = pack2(As[k][ty*8+i]);
                ffma2(acc[i][0], a2, w20);
                ffma2(acc[i][1], a2, w21);
            }
        }
        __syncthreads();
    }
    #pragma unroll
    for (int i = 0; i < 8; i++){
        int m = m0 + ty*8 + i;
        #pragma unroll
        for (int j = 0; j < 2; j++){
            float lo, hi; unpack2(acc[i][j], lo, hi);
            int n = n0 + tx*4 + 2*j;
            g_sc[(size_t)m*H + n]     = tanhf(lo + bias[n]);
            g_sc[(size_t)m*H + n + 1] = tanhf(hi + bias[n+1]);
        }
    }
}

// ---------------- score_c[b,s] = tanh(sc[m,:] . state[b,:]) + mask ----------------
__global__ void k_scorec(const float* __restrict__ state, const int* __restrict__ encoded_idx){
    int warp = threadIdx.x >> 5, lane = threadIdx.x & 31;
    int m = blockIdx.x*8 + warp;                 // m in [0, 32768)
    int b = m >> 9;
    const float* row = g_sc + (size_t)m*H;
    const float* st  = state + (size_t)b*H;
    float s = 0.f;
    for (int k = lane; k < H; k += 32) s = fmaf(row[k], st[k], s);
    #pragma unroll
    for (int off = 16; off; off >>= 1) s += __shfl_xor_sync(0xffffffffu, s, off);
    if (lane == 0){
        float v = tanhf(s);
        if (encoded_idx[m] == 0) v -= 1000.f;
        g_scorec[m] = v;
    }
}

// ---------------- per-row softmax stats over concat(score_g, score_c) ----------------
__global__ void k_rowstats(){
    int b = blockIdx.x;
    __shared__ float red[256];
    const float* sg = g_scoreg + (size_t)b*V;
    const float* sc = g_scorec + b*S;
    float mx = -1e30f;
    for (int i = threadIdx.x; i < V; i += 256) mx = fmaxf(mx, sg[i]);
    for (int i = threadIdx.x; i < S; i += 256) mx = fmaxf(mx, sc[i]);
    red[threadIdx.x] = mx; __syncthreads();
    for (int st = 128; st; st >>= 1){
        if (threadIdx.x < st) red[threadIdx.x] = fmaxf(red[threadIdx.x], red[threadIdx.x+st]);
        __syncthreads();
    }
    mx = red[0];
    __syncthreads();
    float sm = 0.f;
    for (int i = threadIdx.x; i < V; i += 256) sm += expf(sg[i] - mx);
    for (int i = threadIdx.x; i < S; i += 256) sm += expf(sc[i] - mx);
    red[threadIdx.x] = sm; __syncthreads();
    for (int st = 128; st; st >>= 1){
        if (threadIdx.x < st) red[threadIdx.x] += red[threadIdx.x+st];
        __syncthreads();
    }
    if (threadIdx.x == 0){ g_rowmax[b] = mx; g_rowsum[b] = red[0]; }
}

// ---------------- out[:, :V] = prob_g, out[:, V:] = 1e-4 ----------------
__global__ void k_writeout(float* __restrict__ out){
    long long i = (long long)blockIdx.x*256 + threadIdx.x;
    if (i >= (long long)B*OUTW) return;
    int b = (int)(i / OUTW);
    int c = (int)(i - (long long)b*OUTW);
    float v;
    if (c < V) v = expf(g_scoreg[(size_t)b*V + c] - g_rowmax[b]) / g_rowsum[b];
    else       v = 1e-4f;
    out[i] = v;
}

// ---------------- scatter prob_c into out, compute weighted_out ----------------
__global__ void k_tail(float* __restrict__ out, float* __restrict__ out_w,
                       const int* __restrict__ encoded_idx, const int* __restrict__ input_idx,
                       const float* __restrict__ encoded){
    int b = blockIdx.x;
    __shared__ float pc[S];
    __shared__ float attn[S];
    __shared__ int   icnt[256];
    float mx  = g_rowmax[b];
    float inv = 1.f / g_rowsum[b];
    int target = input_idx[b];
    int c = 0;
    for (int s = threadIdx.x; s < S; s += 256){
        float p = expf(g_scorec[b*S + s] - mx) * inv;
        pc[s] = p;
        if (encoded_idx[b*S + s] == target) c++;
    }
    icnt[threadIdx.x] = c; __syncthreads();
    for (int st = 128; st; st >>= 1){
        if (threadIdx.x < st) icnt[threadIdx.x] += icnt[threadIdx.x+st];
        __syncthreads();
    }
    int ssum = icnt[0];
    float scale = (ssum > 1) ? 1.f/(float)ssum : 1.f;
    for (int s = threadIdx.x; s < S; s += 256){
        int idx = encoded_idx[b*S + s];
        atomicAdd(&out[(size_t)b*OUTW + idx], pc[s]);
        attn[s] = (idx == target) ? pc[s]*scale : 0.f;
    }
    __syncthreads();
    float acc[8] = {0.f,0.f,0.f,0.f,0.f,0.f,0.f,0.f};
    const float* eb = encoded + (size_t)b*S*(2*H);
    for (int s = 0; s < S; s++){
        float a = attn[s];
        if (a != 0.f){
            const float* er = eb + (size_t)s*(2*H);
            #pragma unroll
            for (int j = 0; j < 8; j++)
                acc[j] = fmaf(a, er[threadIdx.x + j*256], acc[j]);
        }
    }
    #pragma unroll
    for (int j = 0; j < 8; j++)
        out_w[b*(2*H) + threadIdx.x + j*256] = acc[j];
}

// ---------------- launch ----------------
extern "C" void kernel_launch(void* const* d_in, const int* in_sizes, int n_in,
                              void* d_out, int out_size){
    const int*   input_idx   = (const int*)  d_in[0];
    const float* encoded     = (const float*)d_in[1];
    const int*   encoded_idx = (const int*)  d_in[2];
    const float* prev_state  = (const float*)d_in[3];
    const float* weighted    = (const float*)d_in[4];
    int off = 0;
    const int* order = nullptr;
    if (n_in >= 17 && in_sizes[5] == 1){ order = (const int*)d_in[5]; off = 1; }
    const float* embed  = (const float*)d_in[5+off];
    const float* gru_wi = (const float*)d_in[6+off];
    const float* gru_wh = (const float*)d_in[7+off];
    const float* gru_bi = (const float*)d_in[8+off];
    const float* gru_bh = (const float*)d_in[9+off];
    const float* Ws_w   = (const float*)d_in[10+off];
    const float* Ws_b   = (const float*)d_in[11+off];
    const float* Wg_w   = (const float*)d_in[12+off];
    const float* Wg_b   = (const float*)d_in[13+off];
    const float* Wc_w   = (const float*)d_in[14+off];
    const float* Wc_b   = (const float*)d_in[15+off];
    int has_order = (order != nullptr);
    if (!order) order = input_idx;   // dummy pointer, never dereferenced when has_order==0

    float* out       = (float*)d_out;
    float* out_state = out + (size_t)B*OUTW;
    float* out_w     = out_state + (size_t)B*H;

    static float *p_x = nullptr, *p_prev, *p_gi, *p_gh, *p_scoreg;
    if (!p_x){
        cudaGetSymbolAddress((void**)&p_x,      g_x);
        cudaGetSymbolAddress((void**)&p_prev,   g_prev);
        cudaGetSymbolAddress((void**)&p_gi,     g_gi);
        cudaGetSymbolAddress((void**)&p_gh,     g_gh);
        cudaGetSymbolAddress((void**)&p_scoreg, g_scoreg);
    }

    k_prep_x    <<<B, 256>>>(input_idx, embed, weighted, order, has_order);
    k_prep_state<<<(B*H)/256, 256>>>(prev_state, encoded, Ws_w, Ws_b, order, has_order);

    k_gemm64<<<TH/64, 256>>>(p_x,   gru_wi, gru_bi, p_gi, TH, KX);
    k_gemm64<<<TH/64, 256>>>(p_prev, gru_wh, gru_bh, p_gh, TH, H);
    k_combine<<<(B*H)/256, 256>>>(out_state);

    k_gemm64<<<(V+63)/64, 256>>>(out_state, Wg_w, Wg_b, p_scoreg, V, H);
    k_gemm_sc<<<dim3(H/64, MS/128), 256>>>(encoded, Wc_w, Wc_b);

    k_scorec  <<<MS/8, 256>>>(out_state, encoded_idx);
    k_rowstats<<<B, 256>>>();
    k_writeout<<<((long long)B*OUTW + 255)/256, 256>>>(out);
    k_tail    <<<B, 256>>>(out, out_w, encoded_idx, input_idx, encoded);
}

// round 3
// speedup vs baseline: 3.1833x; 3.1833x over previous
#include <cuda_runtime.h>
#include <cuda_bf16.h>
#include <cstdint>

#define B   64
#define S   512
#define V   50257
#define E   512
#define H   1024
#define OOV 12
#define OUTW (V + OOV)     // 50269
#define KX  (E + 2*H)      // 2560
#define TH  (3*H)          // 3072
#define MS  (B*S)          // 32768
#define KC  (2*H)          // 2048  (K of the big GEMM)
#define NCHUNK 32          // 2048 / 64

// tcgen05 only exists in the arch-specific ('a') device pass. The harness also
// builds a compute_103 (non-a) PTX pass; give it an empty stub there.
#if defined(__CUDA_ARCH_FEAT_SM103_ALL) || defined(__CUDA_ARCH_FEAT_SM100_ALL)
#define HAS_TC 1
#else
#define HAS_TC 0
#endif

// ---------------- scratch (device globals; no allocation allowed) ----------------
__device__ float g_x[B*KX];
__device__ float g_prev[B*H];
__device__ float g_gi[B*TH];
__device__ float g_gh[B*TH];
__device__ float g_scoreg[(size_t)B*V];
__device__ float g_scorec[B*S];
__device__ float g_sc[(size_t)MS*H];   // 134 MB
__device__ float g_rowmax[B];
__device__ float g_rowsum[B];
__device__ __nv_bfloat16 g_Wc_hi[H*KC];
__device__ __nv_bfloat16 g_Wc_lo[H*KC];

typedef unsigned long long u64;

// ---------------- f32x2 helpers (SIMT GEMMs) ----------------
__device__ __forceinline__ u64 pack2(float x){
    u64 r; asm("mov.b64 %0, {%1, %1};" : "=l"(r) : "f"(x)); return r;
}
__device__ __forceinline__ void ffma2(u64& d, u64 a, u64 b){
    asm("fma.rn.f32x2 %0, %1, %2, %0;" : "+l"(d) : "l"(a), "l"(b));
}
__device__ __forceinline__ void unpack2(u64 v, float& lo, float& hi){
    asm("mov.b64 {%0, %1}, %2;" : "=f"(lo), "=f"(hi) : "l"(v));
}

__device__ __forceinline__ void split_bf16(float x, uint16_t& h, uint16_t& l){
    __nv_bfloat16 bh = __float2bfloat16_rn(x);
    __nv_bfloat16 bl = __float2bfloat16_rn(x - __bfloat162float(bh));
    h = __bfloat16_as_ushort(bh);
    l = __bfloat16_as_ushort(bl);
}

// ---------------- convert Wc -> bf16 hi/lo (once per launch) ----------------
__global__ void k_convB(const float* __restrict__ W){
    size_t i = ((size_t)blockIdx.x*256 + threadIdx.x)*4;   // H*KC = 2097152 elems
    float4 w = *(const float4*)(W + i);
    uint16_t h0,h1,h2,h3,l0,l1,l2,l3;
    split_bf16(w.x,h0,l0); split_bf16(w.y,h1,l1); split_bf16(w.z,h2,l2); split_bf16(w.w,h3,l3);
    uint2 hv = make_uint2((uint32_t)h0 | ((uint32_t)h1<<16), (uint32_t)h2 | ((uint32_t)h3<<16));
    uint2 lv = make_uint2((uint32_t)l0 | ((uint32_t)l1<<16), (uint32_t)l2 | ((uint32_t)l3<<16));
    *(uint2*)((char*)g_Wc_hi + i*2) = hv;
    *(uint2*)((char*)g_Wc_lo + i*2) = lv;
}

// ---------------- tcgen05 GEMM: g_sc = tanh(encoded @ Wc^T + bias) ----------------
#define STG_SZ 98304
#define T_AH 0
#define T_AL 16384
#define T_BH 32768
#define T_BL 65536
#define TILE_OFF(stg, t) (1024u + (uint32_t)(stg)*STG_SZ + (uint32_t)(t))
#define SMEM_TC (1024 + 2*STG_SZ)

#if HAS_TC
__device__ __forceinline__ uint32_t smem_u32(const void* p){
    uint32_t a;
    asm("{ .reg .u64 t; cvta.to.shared.u64 t, %1; cvt.u32.u64 %0, t; }" : "=r"(a) : "l"(p));
    return a;
}
__device__ __forceinline__ uint32_t elect_one(){
    uint32_t p;
    asm volatile("{ .reg .pred p; elect.sync _|p, 0xFFFFFFFF; selp.b32 %0, 1, 0, p; }" : "=r"(p));
    return p;
}
#define TC_ALLOC(saddr, n)  asm volatile("tcgen05.alloc.cta_group::1.sync.aligned.shared::cta.b32 [%0], %1;" :: "r"((uint32_t)(saddr)), "r"((uint32_t)(n)) : "memory")
#define TC_DEALLOC(t, n)    asm volatile("tcgen05.dealloc.cta_group::1.sync.aligned.b32 %0, %1;" :: "r"(t), "r"((uint32_t)(n)))
#define TC_RELINQ()         asm volatile("tcgen05.relinquish_alloc_permit.cta_group::1.sync.aligned;")
#define TC_COMMIT(mb)       asm volatile("tcgen05.commit.cta_group::1.mbarrier::arrive::one.shared::cluster.b64 [%0];" :: "r"((uint32_t)(mb)) : "memory")
#define TC_FENCE_AFTER()    asm volatile("tcgen05.fence::after_thread_sync;" ::: "memory")
#define TC_FENCE_BEFORE()   asm volatile("tcgen05.fence::before_thread_sync;" ::: "memory")
#define TC_WAIT_LD()        asm volatile("tcgen05.wait::ld.sync.aligned;" ::: "memory")
#define MBAR_INIT(mb, cnt)  asm volatile("mbarrier.init.shared.b64 [%0], %1;" :: "r"((uint32_t)(mb)), "r"((uint32_t)(cnt)) : "memory")
#define MBAR_WAIT(mb, ph) do { \
    uint32_t _m = (uint32_t)(mb); uint32_t _p = (uint32_t)(ph); uint32_t _d; \
    asm volatile("{ .reg .pred p; mbarrier.try_wait.parity.acquire.cta.shared::cta.b64 p, [%1], %2; selp.b32 %0, 1, 0, p; }" \
        : "=r"(_d) : "r"(_m), "r"(_p) : "memory"); \
    if (!_d) { \
        asm volatile("{ .reg .pred P1; WL_%=: mbarrier.try_wait.parity.acquire.cta.shared::cta.b64 P1, [%0], %1, 0x989680; @P1 bra.uni WD_%=; bra.uni WL_%=; WD_%=: }" \
            :: "r"(_m), "r"(_p) : "memory"); \
    } } while(0)

static constexpr uint64_t SMEM_DESC_BASE_SW128 =
    (uint64_t(2)  << 61) | (uint64_t(1) << 46) | (uint64_t(64) << 32) | (uint64_t(1) << 16);
#define MK_DESC(a) (SMEM_DESC_BASE_SW128 | ((uint64_t)((a) >> 4) & 0x3FFF))

#define TC_LD_X32(r, t) \
    asm volatile("tcgen05.ld.sync.aligned.32x32b.x32.b32 " \
        "{%0,%1,%2,%3,%4,%5,%6,%7,%8,%9,%10,%11,%12,%13,%14,%15," \
        "%16,%17,%18,%19,%20,%21,%22,%23,%24,%25,%26,%27,%28,%29,%30,%31}, [%32];" \
        : "=r"((r)[0]),"=r"((r)[1]),"=r"((r)[2]),"=r"((r)[3]),"=r"((r)[4]),"=r"((r)[5]),"=r"((r)[6]),"=r"((r)[7]), \
          "=r"((r)[8]),"=r"((r)[9]),"=r"((r)[10]),"=r"((r)[11]),"=r"((r)[12]),"=r"((r)[13]),"=r"((r)[14]),"=r"((r)[15]), \
          "=r"((r)[16]),"=r"((r)[17]),"=r"((r)[18]),"=r"((r)[19]),"=r"((r)[20]),"=r"((r)[21]),"=r"((r)[22]),"=r"((r)[23]), \
          "=r"((r)[24]),"=r"((r)[25]),"=r"((r)[26]),"=r"((r)[27]),"=r"((r)[28]),"=r"((r)[29]),"=r"((r)[30]),"=r"((r)[31]) \
        : "r"(t))

__device__ __forceinline__ void mma_f16_ss(uint32_t d, uint64_t a, uint64_t b, uint32_t idesc, uint32_t en){
    asm volatile("{ .reg .pred p; setp.ne.u32 p, %4, 0;"
        " tcgen05.mma.cta_group::1.kind::f16 [%0], %1, %2, %3, {%5,%5,%5,%5}, p; }"
        :: "r"(d), "l"(a), "l"(b), "r"(idesc), "r"(en), "r"(0u) : "memory");
}
#endif // HAS_TC

__global__ void __launch_bounds__(256, 1) k_tc_sc(const float* __restrict__ A,
        const __nv_bfloat16* __restrict__ Bh, const __nv_bfloat16* __restrict__ Bl,
        const float* __restrict__ bias){
#if HAS_TC
    extern __shared__ char smem[];
    uint32_t sb = smem_u32(smem);
    int tid = threadIdx.x, wid = tid >> 5, lid = tid & 31;
    int n0 = blockIdx.x * 256, m0 = blockIdx.y * 128;

    if (wid == 0){ TC_ALLOC(sb + 0, 256); TC_RELINQ(); }
    if (tid == 0){ MBAR_INIT(sb + 8, 1); MBAR_INIT(sb + 16, 1); }
    __syncthreads();
    uint32_t tmem;
    asm volatile("ld.shared.b32 %0, [%1];" : "=r"(tmem) : "r"(sb));

    auto load_chunk = [&](int c, int stg){
        int k0 = c * 64;
        // A: 128 rows x 64 fp32 -> bf16 hi/lo tiles (128B/row, SW128)
        #pragma unroll
        for (int it = 0; it < 8; it++){
            int i = tid + it*256;
            int row = i >> 4, g = i & 15;
            float4 a4 = *(const float4*)(A + (size_t)(m0+row)*KC + k0 + g*4);
            uint16_t h0,h1,h2,h3,l0,l1,l2,l3;
            split_bf16(a4.x,h0,l0); split_bf16(a4.y,h1,l1);
            split_bf16(a4.z,h2,l2); split_bf16(a4.w,h3,l3);
            uint2 hv = make_uint2((uint32_t)h0 | ((uint32_t)h1<<16), (uint32_t)h2 | ((uint32_t)h3<<16));
            uint2 lv = make_uint2((uint32_t)l0 | ((uint32_t)l1<<16), (uint32_t)l2 | ((uint32_t)l3<<16));
            uint32_t off = (uint32_t)(row*128 + g*8);
            uint32_t sw  = off ^ ((off >> 3) & 0x70);
            *(uint2*)(smem + TILE_OFF(stg, T_AH) + sw) = hv;
            *(uint2*)(smem + TILE_OFF(stg, T_AL) + sw) = lv;
        }
        // B: 256 rows x 64 bf16 (pre-split), 128B/row, SW128
        #pragma unroll
        for (int it = 0; it < 8; it++){
            int i = tid + it*256;
            int row = i >> 3, g = i & 7;
            size_t base = ((size_t)(n0+row)*KC + k0) * 2;
            uint4 h4 = *(const uint4*)((const char*)Bh + base + g*16);
            uint4 l4 = *(const uint4*)((const char*)Bl + base + g*16);
            uint32_t off = (uint32_t)(row*128 + g*16);
            uint32_t sw  = off ^ ((off >> 3) & 0x70);
            *(uint4*)(smem + TILE_OFF(stg, T_BH) + sw) = h4;
            *(uint4*)(smem + TILE_OFF(stg, T_BL) + sw) = l4;
        }
    };

    load_chunk(0, 0);
    asm volatile("fence.proxy.async.shared::cta;" ::: "memory");
    __syncthreads();

    const uint32_t idesc = (1u<<4) | (1u<<7) | (1u<<10) | (32u<<17) | (8u<<24);
    int ph[2] = {0, 0};

    for (int c = 0; c < NCHUNK; c++){
        int stg = c & 1;
        if (wid == 0 && elect_one()){
            uint64_t dAh = MK_DESC(sb + TILE_OFF(stg, T_AH));
            uint64_t dAl = MK_DESC(sb + TILE_OFF(stg, T_AL));
            uint64_t dBh = MK_DESC(sb + TILE_OFF(stg, T_BH));
            uint64_t dBl = MK_DESC(sb + TILE_OFF(stg, T_BL));
            #pragma unroll
            for (int ks = 0; ks < 4; ks++){
                uint64_t o = (uint64_t)(ks*2);
                mma_f16_ss(tmem, dAh + o, dBh + o, idesc, (c==0 && ks==0) ? 0u : 1u);
                mma_f16_ss(tmem, dAh + o, dBl + o, idesc, 1u);
                mma_f16_ss(tmem, dAl + o, dBh + o, idesc, 1u);
            }
            TC_COMMIT(sb + 8 + stg*8);
        }
        if (c + 1 < NCHUNK){
            int nst = stg ^ 1;
            if (c >= 1){ MBAR_WAIT(sb + 8 + nst*8, ph[nst]); ph[nst] ^= 1; }
            load_chunk(c + 1, nst);
            asm volatile("fence.proxy.async.shared::cta;" ::: "memory");
            __syncthreads();
        }
    }
    MBAR_WAIT(sb + 8 + ((NCHUNK-1)&1)*8, ph[(NCHUNK-1)&1]);
    TC_FENCE_AFTER();

    // epilogue: warps 0-3 read D (128 rows x 256 cols fp32), tanh+bias, store
    if (wid < 4){
        int mrow = m0 + wid*32 + lid;
        float* dst = g_sc + (size_t)mrow*H + n0;
        #pragma unroll
        for (int c0 = 0; c0 < 256; c0 += 32){
            uint32_t r[32];
            TC_LD_X32(r, tmem + c0);
            TC_WAIT_LD();
            #pragma unroll
            for (int j = 0; j < 8; j++){
                float4 bv = *(const float4*)(bias + n0 + c0 + j*4);
                float4 v;
                v.x = tanhf(__uint_as_float(r[j*4+0]) + bv.x);
                v.y = tanhf(__uint_as_float(r[j*4+1]) + bv.y);
                v.z = tanhf(__uint_as_float(r[j*4+2]) + bv.z);
                v.w = tanhf(__uint_as_float(r[j*4+3]) + bv.w);
                *(float4*)(dst + c0 + j*4) = v;
            }
        }
        TC_FENCE_BEFORE();
    }
    __syncthreads();
    if (wid == 0) TC_DEALLOC(tmem, 256);
#endif // HAS_TC
}

// ---------------- prep: x = concat(embed[input_idx], weighted) ----------------
__global__ void k_prep_x(const int* __restrict__ input_idx, const float* __restrict__ embed,
                         const float* __restrict__ weighted, const int* __restrict__ order,
                         int has_order){
    int b = blockIdx.x;
    int ord = has_order ? *order : 1;
    int idx = input_idx[b];
    for (int j = threadIdx.x; j < KX; j += blockDim.x){
        float v;
        if (j < E) v = embed[(size_t)idx*E + j];
        else       v = ord ? weighted[b*(2*H) + (j - E)] : 0.f;
        g_x[b*KX + j] = v;
    }
}

__global__ void k_prep_state(const float* __restrict__ prev_state, const float* __restrict__ encoded,
                             const float* __restrict__ Ws_w, const float* __restrict__ Ws_b,
                             const int* __restrict__ order, int has_order){
    int i = blockIdx.x*blockDim.x + threadIdx.x;
    if (i >= B*H) return;
    int ord = has_order ? *order : 1;
    if (ord){
        g_prev[i] = prev_state[i];
    } else {
        int b = i >> 10, h = i & (H-1);
        const float* e = encoded + ((size_t)b*S + (S-1))*(2*H);
        const float* w = Ws_w + (size_t)h*(2*H);
        float s = Ws_b[h];
        for (int k = 0; k < 2*H; k++) s = fmaf(e[k], w[k], s);
        g_prev[i] = s;
    }
}

// ---------------- generic M=64 GEMM:  C[64][N] = A[64][K] @ W[N][K]^T + bias ----------------
__global__ void __launch_bounds__(256) k_gemm64(const float* __restrict__ A, const float* __restrict__ W,
                                                const float* __restrict__ bias, float* __restrict__ C,
                                                int N, int K){
    __shared__ __align__(16) float As[16][68];
    __shared__ __align__(16) float Ws[16][68];
    int n0  = blockIdx.x * 64;
    int tid = threadIdx.x;
    int tx  = tid & 15, ty = tid >> 4;
    u64 acc[4][2] = {};
    for (int k0 = 0; k0 < K; k0 += 16){
        int row = tid >> 2;
        int kk  = (tid & 3) << 2;
        float4 a4 = *(const float4*)(A + (size_t)row*K + k0 + kk);
        As[kk+0][row]=a4.x; As[kk+1][row]=a4.y; As[kk+2][row]=a4.z; As[kk+3][row]=a4.w;
        int wr = n0 + row;
        float4 w4 = make_float4(0.f,0.f,0.f,0.f);
        if (wr < N) w4 = *(const float4*)(W + (size_t)wr*K + k0 + kk);
        Ws[kk+0][row]=w4.x; Ws[kk+1][row]=w4.y; Ws[kk+2][row]=w4.z; Ws[kk+3][row]=w4.w;
        __syncthreads();
        #pragma unroll
        for (int k = 0; k < 16; k++){
            u64 w20 = *(const u64*)&Ws[k][tx*4];
            u64 w21 = *(const u64*)&Ws[k][tx*4+2];
            #pragma unroll
            for (int i = 0; i < 4; i++){
                u64 a2 = pack2(As[k][ty*4+i]);
                ffma2(acc[i][0], a2, w20);
                ffma2(acc[i][1], a2, w21);
            }
        }
        __syncthreads();
    }
    #pragma unroll
    for (int i = 0; i < 4; i++){
        int m = ty*4 + i;
        #pragma unroll
        for (int j = 0; j < 2; j++){
            float lo, hi; unpack2(acc[i][j], lo, hi);
            int n = n0 + tx*4 + 2*j;
            if (n   < N) C[(size_t)m*N + n]   = lo + bias[n];
            if (n+1 < N) C[(size_t)m*N + n+1] = hi + bias[n+1];
        }
    }
}

// ---------------- GRU combine ----------------
__global__ void k_combine(float* __restrict__ out_state){
    int i = blockIdx.x*blockDim.x + threadIdx.x;
    if (i >= B*H) return;
    int b = i >> 10, h = i & (H-1);
    const float* gi = g_gi + b*TH;
    const float* gh = g_gh + b*TH;
    float r = 1.f/(1.f + expf(-(gi[h]        + gh[h])));
    float z = 1.f/(1.f + expf(-(gi[H + h]    + gh[H + h])));
    float n = tanhf(gi[2*H + h] + r*gh[2*H + h]);
    out_state[i] = (1.f - z)*n + z*g_prev[i];
}

// ---------------- score_c[b,s] = tanh(sc[m,:] . state[b,:]) + mask ----------------
__global__ void k_scorec(const float* __restrict__ state, const int* __restrict__ encoded_idx){
    int warp = threadIdx.x >> 5, lane = threadIdx.x & 31;
    int m = blockIdx.x*8 + warp;
    int b = m >> 9;
    const float* row = g_sc + (size_t)m*H;
    const float* st  = state + (size_t)b*H;
    float s = 0.f;
    for (int k = lane; k < H; k += 32) s = fmaf(row[k], st[k], s);
    #pragma unroll
    for (int off = 16; off; off >>= 1) s += __shfl_xor_sync(0xffffffffu, s, off);
    if (lane == 0){
        float v = tanhf(s);
        if (encoded_idx[m] == 0) v -= 1000.f;
        g_scorec[m] = v;
    }
}

// ---------------- per-row softmax stats over concat(score_g, score_c) ----------------
__global__ void k_rowstats(){
    int b = blockIdx.x;
    __shared__ float red[256];
    const float* sg = g_scoreg + (size_t)b*V;
    const float* sc = g_scorec + b*S;
    float mx = -1e30f;
    for (int i = threadIdx.x; i < V; i += 256) mx = fmaxf(mx, sg[i]);
    for (int i = threadIdx.x; i < S; i += 256) mx = fmaxf(mx, sc[i]);
    red[threadIdx.x] = mx; __syncthreads();
    for (int st = 128; st; st >>= 1){
        if (threadIdx.x < st) red[threadIdx.x] = fmaxf(red[threadIdx.x], red[threadIdx.x+st]);
        __syncthreads();
    }
    mx = red[0];
    __syncthreads();
    float sm = 0.f;
    for (int i = threadIdx.x; i < V; i += 256) sm += expf(sg[i] - mx);
    for (int i = threadIdx.x; i < S; i += 256) sm += expf(sc[i] - mx);
    red[threadIdx.x] = sm; __syncthreads();
    for (int st = 128; st; st >>= 1){
        if (threadIdx.x < st) red[threadIdx.x] += red[threadIdx.x+st];
        __syncthreads();
    }
    if (threadIdx.x == 0){ g_rowmax[b] = mx; g_rowsum[b] = red[0]; }
}

// ---------------- out[:, :V] = prob_g, out[:, V:] = 1e-4 ----------------
__global__ void k_writeout(float* __restrict__ out){
    long long i = (long long)blockIdx.x*256 + threadIdx.x;
    if (i >= (long long)B*OUTW) return;
    int b = (int)(i / OUTW);
    int c = (int)(i - (long long)b*OUTW);
    float v;
    if (c < V) v = expf(g_scoreg[(size_t)b*V + c] - g_rowmax[b]) / g_rowsum[b];
    else       v = 1e-4f;
    out[i] = v;
}

// ---------------- scatter prob_c into out, compute weighted_out ----------------
__global__ void k_tail(float* __restrict__ out, float* __restrict__ out_w,
                       const int* __restrict__ encoded_idx, const int* __restrict__ input_idx,
                       const float* __restrict__ encoded){
    int b = blockIdx.x;
    __shared__ float pc[S];
    __shared__ float attn[S];
    __shared__ int   icnt[256];
    float mx  = g_rowmax[b];
    float inv = 1.f / g_rowsum[b];
    int target = input_idx[b];
    int c = 0;
    for (int s = threadIdx.x; s < S; s += 256){
        float p = expf(g_scorec[b*S + s] - mx) * inv;
        pc[s] = p;
        if (encoded_idx[b*S + s] == target) c++;
    }
    icnt[threadIdx.x] = c; __syncthreads();
    for (int st = 128; st; st >>= 1){
        if (threadIdx.x < st) icnt[threadIdx.x] += icnt[threadIdx.x+st];
        __syncthreads();
    }
    int ssum = icnt[0];
    float scale = (ssum > 1) ? 1.f/(float)ssum : 1.f;
    for (int s = threadIdx.x; s < S; s += 256){
        int idx = encoded_idx[b*S + s];
        atomicAdd(&out[(size_t)b*OUTW + idx], pc[s]);
        attn[s] = (idx == target) ? pc[s]*scale : 0.f;
    }
    __syncthreads();
    float acc[8] = {0.f,0.f,0.f,0.f,0.f,0.f,0.f,0.f};
    const float* eb = encoded + (size_t)b*S*(2*H);
    for (int s = 0; s < S; s++){
        float a = attn[s];
        if (a != 0.f){
            const float* er = eb + (size_t)s*(2*H);
            #pragma unroll
            for (int j = 0; j < 8; j++)
                acc[j] = fmaf(a, er[threadIdx.x + j*256], acc[j]);
        }
    }
    #pragma unroll
    for (int j = 0; j < 8; j++)
        out_w[b*(2*H) + threadIdx.x + j*256] = acc[j];
}

// ---------------- launch ----------------
extern "C" void kernel_launch(void* const* d_in, const int* in_sizes, int n_in,
                              void* d_out, int out_size){
    const int*   input_idx   = (const int*)  d_in[0];
    const float* encoded     = (const float*)d_in[1];
    const int*   encoded_idx = (const int*)  d_in[2];
    const float* prev_state  = (const float*)d_in[3];
    const float* weighted    = (const float*)d_in[4];
    int off = 0;
    const int* order = nullptr;
    if (n_in >= 17 && in_sizes[5] == 1){ order = (const int*)d_in[5]; off = 1; }
    const float* embed  = (const float*)d_in[5+off];
    const float* gru_wi = (const float*)d_in[6+off];
    const float* gru_wh = (const float*)d_in[7+off];
    const float* gru_bi = (const float*)d_in[8+off];
    const float* gru_bh = (const float*)d_in[9+off];
    const float* Ws_w   = (const float*)d_in[10+off];
    const float* Ws_b   = (const float*)d_in[11+off];
    const float* Wg_w   = (const float*)d_in[12+off];
    const float* Wg_b   = (const float*)d_in[13+off];
    const float* Wc_w   = (const float*)d_in[14+off];
    const float* Wc_b   = (const float*)d_in[15+off];
    int has_order = (order != nullptr);
    if (!order) order = input_idx;

    float* out       = (float*)d_out;
    float* out_state = out + (size_t)B*OUTW;
    float* out_w     = out_state + (size_t)B*H;

    static float *p_x = nullptr, *p_prev, *p_gi, *p_gh, *p_scoreg;
    static __nv_bfloat16 *p_Bh, *p_Bl;
    if (!p_x){
        cudaGetSymbolAddress((void**)&p_x,      g_x);
        cudaGetSymbolAddress((void**)&p_prev,   g_prev);
        cudaGetSymbolAddress((void**)&p_gi,     g_gi);
        cudaGetSymbolAddress((void**)&p_gh,     g_gh);
        cudaGetSymbolAddress((void**)&p_scoreg, g_scoreg);
        cudaGetSymbolAddress((void**)&p_Bh,     g_Wc_hi);
        cudaGetSymbolAddress((void**)&p_Bl,     g_Wc_lo);
        cudaFuncSetAttribute(k_tc_sc, cudaFuncAttributeMaxDynamicSharedMemorySize, SMEM_TC);
    }

    k_prep_x    <<<B, 256>>>(input_idx, embed, weighted, order, has_order);
    k_prep_state<<<(B*H)/256, 256>>>(prev_state, encoded, Ws_w, Ws_b, order, has_order);

    // convert Wc, then big tensor-core GEMM
    k_convB<<<(H*KC)/1024, 256>>>(Wc_w);

    k_gemm64<<<TH/64, 256>>>(p_x,    gru_wi, gru_bi, p_gi, TH, KX);
    k_gemm64<<<TH/64, 256>>>(p_prev, gru_wh, gru_bh, p_gh, TH, H);
    k_combine<<<(B*H)/256, 256>>>(out_state);

    k_gemm64<<<(V+63)/64, 256>>>(out_state, Wg_w, Wg_b, p_scoreg, V, H);

    k_tc_sc<<<dim3(H/256, MS/128), 256, SMEM_TC>>>(encoded, p_Bh, p_Bl, Wc_b);

    k_scorec  <<<MS/8, 256>>>(out_state, encoded_idx);
    k_rowstats<<<B, 256>>>();
    k_writeout<<<((long long)B*OUTW + 255)/256, 256>>>(out);
    k_tail    <<<B, 256>>>(out, out_w, encoded_idx, input_idx, encoded);
}

// round 4
// speedup vs baseline: 4.3652x; 1.3713x over previous
#include <cuda_runtime.h>
#include <cuda_bf16.h>
#include <cstdint>

#define B   64
#define S   512
#define V   50257
#define E   512
#define H   1024
#define OOV 12
#define OUTW (V + OOV)     // 50269
#define KX  (E + 2*H)      // 2560
#define TH  (3*H)          // 3072
#define MS  (B*S)          // 32768
#define KC  (2*H)          // 2048

#if defined(__CUDA_ARCH_FEAT_SM103_ALL) || defined(__CUDA_ARCH_FEAT_SM100_ALL)
#define HAS_TC 1
#else
#define HAS_TC 0
#endif

// ---------------- scratch ----------------
__device__ float g_prev[B*H];
__device__ float g_gi[B*TH];
__device__ float g_gh[B*TH];
__device__ float g_scoreg[(size_t)B*V];
__device__ float g_scorec[B*S];
__device__ float g_scorec_raw[B*S];
__device__ float g_rowmax[B];
__device__ float g_rowsum[B];
__device__ __nv_bfloat16 g_Wc_hi[H*KC];
__device__ __nv_bfloat16 g_Wc_lo[H*KC];
__device__ __nv_bfloat16 g_x_hi[B*KX],    g_x_lo[B*KX];
__device__ __nv_bfloat16 g_prev_hi[B*H],  g_prev_lo[B*H];
__device__ __nv_bfloat16 g_state_hi[B*H], g_state_lo[B*H];

__device__ __forceinline__ void split_bf16(float x, uint16_t& h, uint16_t& l){
    __nv_bfloat16 bh = __float2bfloat16_rn(x);
    __nv_bfloat16 bl = __float2bfloat16_rn(x - __bfloat162float(bh));
    h = __bfloat16_as_ushort(bh);
    l = __bfloat16_as_ushort(bl);
}

// ---------------- convert Wc -> bf16 hi/lo ----------------
__global__ void k_convB(const float* __restrict__ W){
    size_t i = ((size_t)blockIdx.x*256 + threadIdx.x)*4;
    float4 w = *(const float4*)(W + i);
    uint16_t h0,h1,h2,h3,l0,l1,l2,l3;
    split_bf16(w.x,h0,l0); split_bf16(w.y,h1,l1); split_bf16(w.z,h2,l2); split_bf16(w.w,h3,l3);
    uint2 hv = make_uint2((uint32_t)h0 | ((uint32_t)h1<<16), (uint32_t)h2 | ((uint32_t)h3<<16));
    uint2 lv = make_uint2((uint32_t)l0 | ((uint32_t)l1<<16), (uint32_t)l2 | ((uint32_t)l3<<16));
    *(uint2*)((char*)g_Wc_hi + i*2) = hv;
    *(uint2*)((char*)g_Wc_lo + i*2) = lv;
}

// ---------------- tcgen05 plumbing ----------------
#if HAS_TC
__device__ __forceinline__ uint32_t smem_u32(const void* p){
    uint32_t a;
    asm("{ .reg .u64 t; cvta.to.shared.u64 t, %1; cvt.u32.u64 %0, t; }" : "=r"(a) : "l"(p));
    return a;
}
__device__ __forceinline__ uint32_t elect_one(){
    uint32_t p;
    asm volatile("{ .reg .pred p; elect.sync _|p, 0xFFFFFFFF; selp.b32 %0, 1, 0, p; }" : "=r"(p));
    return p;
}
#define TC_ALLOC(saddr, n)  asm volatile("tcgen05.alloc.cta_group::1.sync.aligned.shared::cta.b32 [%0], %1;" :: "r"((uint32_t)(saddr)), "r"((uint32_t)(n)) : "memory")
#define TC_DEALLOC(t, n)    asm volatile("tcgen05.dealloc.cta_group::1.sync.aligned.b32 %0, %1;" :: "r"(t), "r"((uint32_t)(n)))
#define TC_RELINQ()         asm volatile("tcgen05.relinquish_alloc_permit.cta_group::1.sync.aligned;")
#define TC_COMMIT(mb)       asm volatile("tcgen05.commit.cta_group::1.mbarrier::arrive::one.shared::cluster.b64 [%0];" :: "r"((uint32_t)(mb)) : "memory")
#define TC_FENCE_AFTER()    asm volatile("tcgen05.fence::after_thread_sync;" ::: "memory")
#define TC_FENCE_BEFORE()   asm volatile("tcgen05.fence::before_thread_sync;" ::: "memory")
#define TC_WAIT_LD()        asm volatile("tcgen05.wait::ld.sync.aligned;" ::: "memory")
#define MBAR_INIT(mb, cnt)  asm volatile("mbarrier.init.shared.b64 [%0], %1;" :: "r"((uint32_t)(mb)), "r"((uint32_t)(cnt)) : "memory")
#define MBAR_WAIT(mb, ph) do { \
    uint32_t _m = (uint32_t)(mb); uint32_t _p = (uint32_t)(ph); uint32_t _d; \
    asm volatile("{ .reg .pred p; mbarrier.try_wait.parity.acquire.cta.shared::cta.b64 p, [%1], %2; selp.b32 %0, 1, 0, p; }" \
        : "=r"(_d) : "r"(_m), "r"(_p) : "memory"); \
    if (!_d) { \
        asm volatile("{ .reg .pred P1; WL_%=: mbarrier.try_wait.parity.acquire.cta.shared::cta.b64 P1, [%0], %1, 0x989680; @P1 bra.uni WD_%=; bra.uni WL_%=; WD_%=: }" \
            :: "r"(_m), "r"(_p) : "memory"); \
    } } while(0)

static constexpr uint64_t SMEM_DESC_BASE_SW128 =
    (uint64_t(2)  << 61) | (uint64_t(1) << 46) | (uint64_t(64) << 32) | (uint64_t(1) << 16);
#define MK_DESC(a) (SMEM_DESC_BASE_SW128 | ((uint64_t)((a) >> 4) & 0x3FFF))

#define TC_LD_X32(r, t) \
    asm volatile("tcgen05.ld.sync.aligned.32x32b.x32.b32 " \
        "{%0,%1,%2,%3,%4,%5,%6,%7,%8,%9,%10,%11,%12,%13,%14,%15," \
        "%16,%17,%18,%19,%20,%21,%22,%23,%24,%25,%26,%27,%28,%29,%30,%31}, [%32];" \
        : "=r"((r)[0]),"=r"((r)[1]),"=r"((r)[2]),"=r"((r)[3]),"=r"((r)[4]),"=r"((r)[5]),"=r"((r)[6]),"=r"((r)[7]), \
          "=r"((r)[8]),"=r"((r)[9]),"=r"((r)[10]),"=r"((r)[11]),"=r"((r)[12]),"=r"((r)[13]),"=r"((r)[14]),"=r"((r)[15]), \
          "=r"((r)[16]),"=r"((r)[17]),"=r"((r)[18]),"=r"((r)[19]),"=r"((r)[20]),"=r"((r)[21]),"=r"((r)[22]),"=r"((r)[23]), \
          "=r"((r)[24]),"=r"((r)[25]),"=r"((r)[26]),"=r"((r)[27]),"=r"((r)[28]),"=r"((r)[29]),"=r"((r)[30]),"=r"((r)[31]) \
        : "r"(t))

__device__ __forceinline__ void mma_f16_ss(uint32_t d, uint64_t a, uint64_t b, uint32_t idesc, uint32_t en){
    asm volatile("{ .reg .pred p; setp.ne.u32 p, %4, 0;"
        " tcgen05.mma.cta_group::1.kind::f16 [%0], %1, %2, %3, {%5,%5,%5,%5}, p; }"
        :: "r"(d), "l"(a), "l"(b), "r"(idesc), "r"(en), "r"(0u) : "memory");
}
#endif // HAS_TC

// ============ big fused GEMM: partial score_c += tanh(enc@Wc^T + b) . state ============
#define HDR_SC 4096
#define STG_SZ 98304
#define T_AH 0
#define T_AL 16384
#define T_BH 32768
#define T_BL 65536
#define TILE_OFF(stg, t) (HDR_SC + (uint32_t)(stg)*STG_SZ + (uint32_t)(t))
#define SMEM_TC (HDR_SC + 2*STG_SZ)
#define NCHUNK_SC 32

__global__ void __launch_bounds__(256, 1) k_tc_sc(const float* __restrict__ A,
        const __nv_bfloat16* __restrict__ Bh, const __nv_bfloat16* __restrict__ Bl,
        const float* __restrict__ bias, const float* __restrict__ state){
#if HAS_TC
    extern __shared__ char smem[];
    uint32_t sb = smem_u32(smem);
    int tid = threadIdx.x, wid = tid >> 5, lid = tid & 31;
    int n0 = blockIdx.x * 256, m0 = blockIdx.y * 128;
    int b  = m0 >> 9;                       // 128-row tile always within one batch row-block
    float* s_state = (float*)(smem + 64);
    float* s_bias  = (float*)(smem + 64 + 1024);

    if (wid == 0){ TC_ALLOC(sb + 0, 256); TC_RELINQ(); }
    if (tid == 0){ MBAR_INIT(sb + 8, 1); MBAR_INIT(sb + 16, 1); }
    s_state[tid] = state[b*H + n0 + tid];
    s_bias[tid]  = bias[n0 + tid];
    __syncthreads();
    uint32_t tmem;
    asm volatile("ld.shared.b32 %0, [%1];" : "=r"(tmem) : "r"(sb));

    auto load_chunk = [&](int c, int stg){
        int k0 = c * 64;
        #pragma unroll
        for (int it = 0; it < 8; it++){
            int i = tid + it*256;
            int row = i >> 4, g = i & 15;
            float4 a4 = *(const float4*)(A + (size_t)(m0+row)*KC + k0 + g*4);
            uint16_t h0,h1,h2,h3,l0,l1,l2,l3;
            split_bf16(a4.x,h0,l0); split_bf16(a4.y,h1,l1);
            split_bf16(a4.z,h2,l2); split_bf16(a4.w,h3,l3);
            uint2 hv = make_uint2((uint32_t)h0 | ((uint32_t)h1<<16), (uint32_t)h2 | ((uint32_t)h3<<16));
            uint2 lv = make_uint2((uint32_t)l0 | ((uint32_t)l1<<16), (uint32_t)l2 | ((uint32_t)l3<<16));
            uint32_t off = (uint32_t)(row*128 + g*8);
            uint32_t sw  = off ^ ((off >> 3) & 0x70);
            *(uint2*)(smem + TILE_OFF(stg, T_AH) + sw) = hv;
            *(uint2*)(smem + TILE_OFF(stg, T_AL) + sw) = lv;
        }
        #pragma unroll
        for (int it = 0; it < 8; it++){
            int i = tid + it*256;
            int row = i >> 3, g = i & 7;
            size_t base = ((size_t)(n0+row)*KC + k0) * 2;
            uint4 h4 = *(const uint4*)((const char*)Bh + base + g*16);
            uint4 l4 = *(const uint4*)((const char*)Bl + base + g*16);
            uint32_t off = (uint32_t)(row*128 + g*16);
            uint32_t sw  = off ^ ((off >> 3) & 0x70);
            *(uint4*)(smem + TILE_OFF(stg, T_BH) + sw) = h4;
            *(uint4*)(smem + TILE_OFF(stg, T_BL) + sw) = l4;
        }
    };

    load_chunk(0, 0);
    asm volatile("fence.proxy.async.shared::cta;" ::: "memory");
    __syncthreads();

    const uint32_t idesc = (1u<<4) | (1u<<7) | (1u<<10) | (32u<<17) | (8u<<24);
    int ph[2] = {0, 0};

    for (int c = 0; c < NCHUNK_SC; c++){
        int stg = c & 1;
        if (wid == 0 && elect_one()){
            uint64_t dAh = MK_DESC(sb + TILE_OFF(stg, T_AH));
            uint64_t dAl = MK_DESC(sb + TILE_OFF(stg, T_AL));
            uint64_t dBh = MK_DESC(sb + TILE_OFF(stg, T_BH));
            uint64_t dBl = MK_DESC(sb + TILE_OFF(stg, T_BL));
            #pragma unroll
            for (int ks = 0; ks < 4; ks++){
                uint64_t o = (uint64_t)(ks*2);
                mma_f16_ss(tmem, dAh + o, dBh + o, idesc, (c==0 && ks==0) ? 0u : 1u);
                mma_f16_ss(tmem, dAh + o, dBl + o, idesc, 1u);
                mma_f16_ss(tmem, dAl + o, dBh + o, idesc, 1u);
            }
            TC_COMMIT(sb + 8 + stg*8);
        }
        if (c + 1 < NCHUNK_SC){
            int nst = stg ^ 1;
            if (c >= 1){ MBAR_WAIT(sb + 8 + nst*8, ph[nst]); ph[nst] ^= 1; }
            load_chunk(c + 1, nst);
            asm volatile("fence.proxy.async.shared::cta;" ::: "memory");
            __syncthreads();
        }
    }
    MBAR_WAIT(sb + 8 + ((NCHUNK_SC-1)&1)*8, ph[(NCHUNK_SC-1)&1]);
    TC_FENCE_AFTER();

    // epilogue: per row m, acc += tanh(D+bias)*state, atomic partial into scorec_raw
    if (wid < 4){
        float acc = 0.f;
        #pragma unroll
        for (int c0 = 0; c0 < 256; c0 += 32){
            uint32_t r[32];
            TC_LD_X32(r, tmem + c0);
            TC_WAIT_LD();
            #pragma unroll
            for (int j = 0; j < 32; j++)
                acc += tanhf(__uint_as_float(r[j]) + s_bias[c0+j]) * s_state[c0+j];
        }
        TC_FENCE_BEFORE();
        atomicAdd(&g_scorec_raw[m0 + wid*32 + lid], acc);
    }
    __syncthreads();
    if (wid == 0) TC_DEALLOC(tmem, 256);
#endif
}

// ============ generic tc GEMM: out[act][w] += (W fp32 -> bf16 hi/lo) x act  ============
// M tile = 128 W-rows, N = 64 activations, K chunked by 64, split-K via blockIdx.y.
#define HDR_W 1024
#define WSTG 49152
#define W_AH 0
#define W_AL 16384
#define W_BH 32768
#define W_BL 40960
#define WT_OFF(stg, t) (HDR_W + (uint32_t)(stg)*WSTG + (uint32_t)(t))
#define SMEM_TW (HDR_W + 2*WSTG)

__global__ void __launch_bounds__(256, 1) k_tcW(const float* __restrict__ W,
        const __nv_bfloat16* __restrict__ act_hi, const __nv_bfloat16* __restrict__ act_lo,
        float* __restrict__ out, int Nw, int K, int kpc, int ldO){
#if HAS_TC
    extern __shared__ char smem[];
    uint32_t sb = smem_u32(smem);
    int tid = threadIdx.x, wid = tid >> 5, lid = tid & 31;
    int m0 = blockIdx.x * 128;
    int k_base = blockIdx.y * kpc * 64;

    if (wid == 0){ TC_ALLOC(sb + 0, 64); TC_RELINQ(); }
    if (tid == 0){ MBAR_INIT(sb + 8, 1); MBAR_INIT(sb + 16, 1); }
    __syncthreads();
    uint32_t tmem;
    asm volatile("ld.shared.b32 %0, [%1];" : "=r"(tmem) : "r"(sb));

    auto load_chunk = [&](int c, int stg){
        int k0 = k_base + c * 64;
        // W: 128 rows x 64 fp32 -> bf16 hi/lo (bounds-checked rows)
        #pragma unroll
        for (int it = 0; it < 8; it++){
            int i = tid + it*256;
            int row = i >> 4, g = i & 15;
            float4 a4 = make_float4(0.f,0.f,0.f,0.f);
            if (m0 + row < Nw) a4 = *(const float4*)(W + (size_t)(m0+row)*K + k0 + g*4);
            uint16_t h0,h1,h2,h3,l0,l1,l2,l3;
            split_bf16(a4.x,h0,l0); split_bf16(a4.y,h1,l1);
            split_bf16(a4.z,h2,l2); split_bf16(a4.w,h3,l3);
            uint2 hv = make_uint2((uint32_t)h0 | ((uint32_t)h1<<16), (uint32_t)h2 | ((uint32_t)h3<<16));
            uint2 lv = make_uint2((uint32_t)l0 | ((uint32_t)l1<<16), (uint32_t)l2 | ((uint32_t)l3<<16));
            uint32_t off = (uint32_t)(row*128 + g*8);
            uint32_t sw  = off ^ ((off >> 3) & 0x70);
            *(uint2*)(smem + WT_OFF(stg, W_AH) + sw) = hv;
            *(uint2*)(smem + WT_OFF(stg, W_AL) + sw) = lv;
        }
        // act: 64 rows x 64 bf16 (pre-split)
        #pragma unroll
        for (int it = 0; it < 2; it++){
            int i = tid + it*256;
            int row = i >> 3, g = i & 7;
            size_t base = ((size_t)row*K + k0) * 2;
            uint4 h4 = *(const uint4*)((const char*)act_hi + base + g*16);
            uint4 l4 = *(const uint4*)((const char*)act_lo + base + g*16);
            uint32_t off = (uint32_t)(row*128 + g*16);
            uint32_t sw  = off ^ ((off >> 3) & 0x70);
            *(uint4*)(smem + WT_OFF(stg, W_BH) + sw) = h4;
            *(uint4*)(smem + WT_OFF(stg, W_BL) + sw) = l4;
        }
    };

    load_chunk(0, 0);
    asm volatile("fence.proxy.async.shared::cta;" ::: "memory");
    __syncthreads();

    const uint32_t idesc = (1u<<4) | (1u<<7) | (1u<<10) | (8u<<17) | (8u<<24);   // N=64, M=128
    int ph[2] = {0, 0};

    for (int c = 0; c < kpc; c++){
        int stg = c & 1;
        if (wid == 0 && elect_one()){
            uint64_t dAh = MK_DESC(sb + WT_OFF(stg, W_AH));
            uint64_t dAl = MK_DESC(sb + WT_OFF(stg, W_AL));
            uint64_t dBh = MK_DESC(sb + WT_OFF(stg, W_BH));
            uint64_t dBl = MK_DESC(sb + WT_OFF(stg, W_BL));
            #pragma unroll
            for (int ks = 0; ks < 4; ks++){
                uint64_t o = (uint64_t)(ks*2);
                mma_f16_ss(tmem, dAh + o, dBh + o, idesc, (c==0 && ks==0) ? 0u : 1u);
                mma_f16_ss(tmem, dAh + o, dBl + o, idesc, 1u);
                mma_f16_ss(tmem, dAl + o, dBh + o, idesc, 1u);
            }
            TC_COMMIT(sb + 8 + stg*8);
        }
        if (c + 1 < kpc){
            int nst = stg ^ 1;
            if (c >= 1){ MBAR_WAIT(sb + 8 + nst*8, ph[nst]); ph[nst] ^= 1; }
            load_chunk(c + 1, nst);
            asm volatile("fence.proxy.async.shared::cta;" ::: "memory");
            __syncthreads();
        }
    }
    MBAR_WAIT(sb + 8 + ((kpc-1)&1)*8, ph[(kpc-1)&1]);
    TC_FENCE_AFTER();

    // epilogue: D[128 W-rows][64 acts]; lane = W-row, reg = act index; atomicAdd transposed
    if (wid < 4){
        uint32_t r0[32], r1[32];
        TC_LD_X32(r0, tmem);
        TC_LD_X32(r1, tmem + 32);
        TC_WAIT_LD();
        TC_FENCE_BEFORE();
        int m = m0 + wid*32 + lid;
        if (m < Nw){
            #pragma unroll
            for (int c = 0; c < 32; c++)
                atomicAdd(out + (size_t)c*ldO + m, __uint_as_float(r0[c]));
            #pragma unroll
            for (int c = 0; c < 32; c++)
                atomicAdd(out + (size_t)(c+32)*ldO + m, __uint_as_float(r1[c]));
        }
    }
    __syncthreads();
    if (wid == 0) TC_DEALLOC(tmem, 64);
#endif
}

// ---------------- prep: x = concat(embed[input_idx], weighted) -> bf16 hi/lo ----------------
__global__ void k_prep_x(const int* __restrict__ input_idx, const float* __restrict__ embed,
                         const float* __restrict__ weighted, const int* __restrict__ order,
                         int has_order){
    int b = blockIdx.x;
    int ord = has_order ? *order : 1;
    int idx = input_idx[b];
    for (int j = threadIdx.x; j < KX; j += blockDim.x){
        float v;
        if (j < E) v = embed[(size_t)idx*E + j];
        else       v = ord ? weighted[b*(2*H) + (j - E)] : 0.f;
        uint16_t h, l; split_bf16(v, h, l);
        g_x_hi[b*KX + j] = __ushort_as_bfloat16(h);
        g_x_lo[b*KX + j] = __ushort_as_bfloat16(l);
    }
}

__global__ void k_prep_state(const float* __restrict__ prev_state, const float* __restrict__ encoded,
                             const float* __restrict__ Ws_w, const float* __restrict__ Ws_b,
                             const int* __restrict__ order, int has_order){
    int i = blockIdx.x*blockDim.x + threadIdx.x;
    if (i >= B*H) return;
    int ord = has_order ? *order : 1;
    float v;
    if (ord){
        v = prev_state[i];
    } else {
        int b = i >> 10, h = i & (H-1);
        const float* e = encoded + ((size_t)b*S + (S-1))*(2*H);
        const float* w = Ws_w + (size_t)h*(2*H);
        float s = Ws_b[h];
        for (int k = 0; k < 2*H; k++) s = fmaf(e[k], w[k], s);
        v = s;
    }
    g_prev[i] = v;
    uint16_t h16, l16; split_bf16(v, h16, l16);
    g_prev_hi[i] = __ushort_as_bfloat16(h16);
    g_prev_lo[i] = __ushort_as_bfloat16(l16);
}

// ---------------- init gi/gh with biases; zero scorec_raw ----------------
__global__ void k_init_gates(const float* __restrict__ bi, const float* __restrict__ bh){
    int i = blockIdx.x*blockDim.x + threadIdx.x;
    if (i < B*TH){
        int j = i % TH;
        g_gi[i] = bi[j];
        g_gh[i] = bh[j];
    }
    if (i < B*S) g_scorec_raw[i] = 0.f;
}

__global__ void k_init_scoreg(const float* __restrict__ Wg_b){
    int n = blockIdx.x*blockDim.x + threadIdx.x;
    int b = blockIdx.y;
    if (n < V) g_scoreg[(size_t)b*V + n] = Wg_b[n];
}

// ---------------- GRU combine -> state fp32 + bf16 hi/lo ----------------
__global__ void k_combine(float* __restrict__ out_state){
    int i = blockIdx.x*blockDim.x + threadIdx.x;
    if (i >= B*H) return;
    int b = i >> 10, h = i & (H-1);
    const float* gi = g_gi + b*TH;
    const float* gh = g_gh + b*TH;
    float r = 1.f/(1.f + expf(-(gi[h]        + gh[h])));
    float z = 1.f/(1.f + expf(-(gi[H + h]    + gh[H + h])));
    float n = tanhf(gi[2*H + h] + r*gh[2*H + h]);
    float st = (1.f - z)*n + z*g_prev[i];
    out_state[i] = st;
    uint16_t h16, l16; split_bf16(st, h16, l16);
    g_state_hi[i] = __ushort_as_bfloat16(h16);
    g_state_lo[i] = __ushort_as_bfloat16(l16);
}

// ---------------- finalize score_c ----------------
__global__ void k_scorec_fin(const int* __restrict__ encoded_idx){
    int m = blockIdx.x*blockDim.x + threadIdx.x;
    float v = tanhf(g_scorec_raw[m]);
    if (encoded_idx[m] == 0) v -= 1000.f;
    g_scorec[m] = v;
}

// ---------------- softmax stats / writeout / tail ----------------
__global__ void k_rowstats(){
    int b = blockIdx.x;
    __shared__ float red[256];
    const float* sg = g_scoreg + (size_t)b*V;
    const float* sc = g_scorec + b*S;
    float mx = -1e30f;
    for (int i = threadIdx.x; i < V; i += 256) mx = fmaxf(mx, sg[i]);
    for (int i = threadIdx.x; i < S; i += 256) mx = fmaxf(mx, sc[i]);
    red[threadIdx.x] = mx; __syncthreads();
    for (int st = 128; st; st >>= 1){
        if (threadIdx.x < st) red[threadIdx.x] = fmaxf(red[threadIdx.x], red[threadIdx.x+st]);
        __syncthreads();
    }
    mx = red[0];
    __syncthreads();
    float sm = 0.f;
    for (int i = threadIdx.x; i < V; i += 256) sm += expf(sg[i] - mx);
    for (int i = threadIdx.x; i < S; i += 256) sm += expf(sc[i] - mx);
    red[threadIdx.x] = sm; __syncthreads();
    for (int st = 128; st; st >>= 1){
        if (threadIdx.x < st) red[threadIdx.x] += red[threadIdx.x+st];
        __syncthreads();
    }
    if (threadIdx.x == 0){ g_rowmax[b] = mx; g_rowsum[b] = red[0]; }
}

__global__ void k_writeout(float* __restrict__ out){
    long long i = (long long)blockIdx.x*256 + threadIdx.x;
    if (i >= (long long)B*OUTW) return;
    int b = (int)(i / OUTW);
    int c = (int)(i - (long long)b*OUTW);
    float v;
    if (c < V) v = expf(g_scoreg[(size_t)b*V + c] - g_rowmax[b]) / g_rowsum[b];
    else       v = 1e-4f;
    out[i] = v;
}

__global__ void k_tail(float* __restrict__ out, float* __restrict__ out_w,
                       const int* __restrict__ encoded_idx, const int* __restrict__ input_idx,
                       const float* __restrict__ encoded){
    int b = blockIdx.x;
    __shared__ float pc[S];
    __shared__ float attn[S];
    __shared__ int   icnt[256];
    float mx  = g_rowmax[b];
    float inv = 1.f / g_rowsum[b];
    int target = input_idx[b];
    int c = 0;
    for (int s = threadIdx.x; s < S; s += 256){
        float p = expf(g_scorec[b*S + s] - mx) * inv;
        pc[s] = p;
        if (encoded_idx[b*S + s] == target) c++;
    }
    icnt[threadIdx.x] = c; __syncthreads();
    for (int st = 128; st; st >>= 1){
        if (threadIdx.x < st) icnt[threadIdx.x] += icnt[threadIdx.x+st];
        __syncthreads();
    }
    int ssum = icnt[0];
    float scale = (ssum > 1) ? 1.f/(float)ssum : 1.f;
    for (int s = threadIdx.x; s < S; s += 256){
        int idx = encoded_idx[b*S + s];
        atomicAdd(&out[(size_t)b*OUTW + idx], pc[s]);
        attn[s] = (idx == target) ? pc[s]*scale : 0.f;
    }
    __syncthreads();
    float acc[8] = {0.f,0.f,0.f,0.f,0.f,0.f,0.f,0.f};
    const float* eb = encoded + (size_t)b*S*(2*H);
    for (int s = 0; s < S; s++){
        float a = attn[s];
        if (a != 0.f){
            const float* er = eb + (size_t)s*(2*H);
            #pragma unroll
            for (int j = 0; j < 8; j++)
                acc[j] = fmaf(a, er[threadIdx.x + j*256], acc[j]);
        }
    }
    #pragma unroll
    for (int j = 0; j < 8; j++)
        out_w[b*(2*H) + threadIdx.x + j*256] = acc[j];
}

// ---------------- launch ----------------
extern "C" void kernel_launch(void* const* d_in, const int* in_sizes, int n_in,
                              void* d_out, int out_size){
    const int*   input_idx   = (const int*)  d_in[0];
    const float* encoded     = (const float*)d_in[1];
    const int*   encoded_idx = (const int*)  d_in[2];
    const float* prev_state  = (const float*)d_in[3];
    const float* weighted    = (const float*)d_in[4];
    int off = 0;
    const int* order = nullptr;
    if (n_in >= 17 && in_sizes[5] == 1){ order = (const int*)d_in[5]; off = 1; }
    const float* embed  = (const float*)d_in[5+off];
    const float* gru_wi = (const float*)d_in[6+off];
    const float* gru_wh = (const float*)d_in[7+off];
    const float* gru_bi = (const float*)d_in[8+off];
    const float* gru_bh = (const float*)d_in[9+off];
    const float* Ws_w   = (const float*)d_in[10+off];
    const float* Ws_b   = (const float*)d_in[11+off];
    const float* Wg_w   = (const float*)d_in[12+off];
    const float* Wg_b   = (const float*)d_in[13+off];
    const float* Wc_w   = (const float*)d_in[14+off];
    const float* Wc_b   = (const float*)d_in[15+off];
    int has_order = (order != nullptr);
    if (!order) order = input_idx;

    float* out       = (float*)d_out;
    float* out_state = out + (size_t)B*OUTW;
    float* out_w     = out_state + (size_t)B*H;

    static float *p_gi = nullptr, *p_gh, *p_scoreg;
    static __nv_bfloat16 *p_Bh, *p_Bl, *p_xh, *p_xl, *p_ph, *p_pl, *p_sh, *p_sl;
    if (!p_gi){
        cudaGetSymbolAddress((void**)&p_gi,     g_gi);
        cudaGetSymbolAddress((void**)&p_gh,     g_gh);
        cudaGetSymbolAddress((void**)&p_scoreg, g_scoreg);
        cudaGetSymbolAddress((void**)&p_Bh,     g_Wc_hi);
        cudaGetSymbolAddress((void**)&p_Bl,     g_Wc_lo);
        cudaGetSymbolAddress((void**)&p_xh,     g_x_hi);
        cudaGetSymbolAddress((void**)&p_xl,     g_x_lo);
        cudaGetSymbolAddress((void**)&p_ph,     g_prev_hi);
        cudaGetSymbolAddress((void**)&p_pl,     g_prev_lo);
        cudaGetSymbolAddress((void**)&p_sh,     g_state_hi);
        cudaGetSymbolAddress((void**)&p_sl,     g_state_lo);
        cudaFuncSetAttribute(k_tc_sc, cudaFuncAttributeMaxDynamicSharedMemorySize, SMEM_TC);
        cudaFuncSetAttribute(k_tcW,   cudaFuncAttributeMaxDynamicSharedMemorySize, SMEM_TW);
    }

    k_prep_x    <<<B, 256>>>(input_idx, embed, weighted, order, has_order);
    k_prep_state<<<(B*H)/256, 256>>>(prev_state, encoded, Ws_w, Ws_b, order, has_order);
    k_init_gates<<<(B*TH + 255)/256, 256>>>(gru_bi, gru_bh);
    k_convB     <<<(H*KC)/1024, 256>>>(Wc_w);

    // GRU gate GEMMs (split-K=2)
    k_tcW<<<dim3(TH/128, 2), 256, SMEM_TW>>>(gru_wi, p_xh, p_xl, p_gi, TH, KX, KX/128, TH);
    k_tcW<<<dim3(TH/128, 2), 256, SMEM_TW>>>(gru_wh, p_ph, p_pl, p_gh, TH, H,  H/128,  TH);
    k_combine<<<(B*H)/256, 256>>>(out_state);

    // score_g = state @ Wg^T + b
    k_init_scoreg<<<dim3((V+255)/256, B), 256>>>(Wg_b);
    k_tcW<<<dim3((V+127)/128, 1), 256, SMEM_TW>>>(Wg_w, p_sh, p_sl, p_scoreg, V, H, H/64, V);

    // fused big GEMM + score_c partials
    k_tc_sc<<<dim3(H/256, MS/128), 256, SMEM_TC>>>(encoded, p_Bh, p_Bl, Wc_b, out_state);
    k_scorec_fin<<<MS/256, 256>>>(encoded_idx);

    k_rowstats<<<B, 256>>>();
    k_writeout<<<((long long)B*OUTW + 255)/256, 256>>>(out);
    k_tail    <<<B, 256>>>(out, out_w, encoded_idx, input_idx, encoded);
}

// round 5
// speedup vs baseline: 4.5916x; 1.0519x over previous
#include <cuda_runtime.h>
#include <cuda_bf16.h>
#include <cstdint>

#define B   64
#define S   512
#define V   50257
#define E   512
#define H   1024
#define OOV 12
#define OUTW (V + OOV)     // 50269
#define KX  (E + 2*H)      // 2560
#define TH  (3*H)          // 3072
#define MS  (B*S)          // 32768
#define KC  (2*H)          // 2048

#if defined(__CUDA_ARCH_FEAT_SM103_ALL) || defined(__CUDA_ARCH_FEAT_SM100_ALL)
#define HAS_TC 1
#else
#define HAS_TC 0
#endif

// ---------------- scratch ----------------
__device__ float g_prev[B*H];
__device__ float g_gi[B*TH];
__device__ float g_gh[B*TH];
__device__ float g_scoreg[(size_t)B*V];
__device__ float g_scorec[B*S];
__device__ float g_scorec_raw[B*S];
__device__ float g_rowmax[B];
__device__ float g_rowsum[B];
__device__ __nv_bfloat16 g_Wc_hi[H*KC];
__device__ __nv_bfloat16 g_Wc_lo[H*KC];
__device__ __nv_bfloat16 g_x_hi[B*KX],    g_x_lo[B*KX];
__device__ __nv_bfloat16 g_prev_hi[B*H],  g_prev_lo[B*H];
__device__ __nv_bfloat16 g_state_hi[B*H], g_state_lo[B*H];

__device__ __forceinline__ void split_bf16(float x, uint16_t& h, uint16_t& l){
    __nv_bfloat16 bh = __float2bfloat16_rn(x);
    __nv_bfloat16 bl = __float2bfloat16_rn(x - __bfloat162float(bh));
    h = __bfloat16_as_ushort(bh);
    l = __bfloat16_as_ushort(bl);
}

// ---------------- convert Wc -> bf16 hi/lo ----------------
__global__ void k_convB(const float* __restrict__ W){
    size_t i = ((size_t)blockIdx.x*256 + threadIdx.x)*4;
    float4 w = *(const float4*)(W + i);
    uint16_t h0,h1,h2,h3,l0,l1,l2,l3;
    split_bf16(w.x,h0,l0); split_bf16(w.y,h1,l1); split_bf16(w.z,h2,l2); split_bf16(w.w,h3,l3);
    uint2 hv = make_uint2((uint32_t)h0 | ((uint32_t)h1<<16), (uint32_t)h2 | ((uint32_t)h3<<16));
    uint2 lv = make_uint2((uint32_t)l0 | ((uint32_t)l1<<16), (uint32_t)l2 | ((uint32_t)l3<<16));
    *(uint2*)((char*)g_Wc_hi + i*2) = hv;
    *(uint2*)((char*)g_Wc_lo + i*2) = lv;
}

// ---------------- tcgen05 plumbing ----------------
#if HAS_TC
__device__ __forceinline__ uint32_t smem_u32(const void* p){
    uint32_t a;
    asm("{ .reg .u64 t; cvta.to.shared.u64 t, %1; cvt.u32.u64 %0, t; }" : "=r"(a) : "l"(p));
    return a;
}
__device__ __forceinline__ uint32_t elect_one(){
    uint32_t p;
    asm volatile("{ .reg .pred p; elect.sync _|p, 0xFFFFFFFF; selp.b32 %0, 1, 0, p; }" : "=r"(p));
    return p;
}
#define TC_ALLOC(saddr, n)  asm volatile("tcgen05.alloc.cta_group::1.sync.aligned.shared::cta.b32 [%0], %1;" :: "r"((uint32_t)(saddr)), "r"((uint32_t)(n)) : "memory")
#define TC_DEALLOC(t, n)    asm volatile("tcgen05.dealloc.cta_group::1.sync.aligned.b32 %0, %1;" :: "r"(t), "r"((uint32_t)(n)))
#define TC_RELINQ()         asm volatile("tcgen05.relinquish_alloc_permit.cta_group::1.sync.aligned;")
#define TC_ALLOC2(saddr, n) asm volatile("tcgen05.alloc.cta_group::2.sync.aligned.shared::cta.b32 [%0], %1;" :: "r"((uint32_t)(saddr)), "r"((uint32_t)(n)) : "memory")
#define TC_DEALLOC2(t, n)   asm volatile("tcgen05.dealloc.cta_group::2.sync.aligned.b32 %0, %1;" :: "r"(t), "r"((uint32_t)(n)))
#define TC_RELINQ2()        asm volatile("tcgen05.relinquish_alloc_permit.cta_group::2.sync.aligned;")
#define TC_COMMIT(mb)       asm volatile("tcgen05.commit.cta_group::1.mbarrier::arrive::one.shared::cluster.b64 [%0];" :: "r"((uint32_t)(mb)) : "memory")
#define TC_COMMIT2_MC(mb, mask) asm volatile("tcgen05.commit.cta_group::2.mbarrier::arrive::one.shared::cluster.multicast::cluster.b64 [%0], %1;" :: "r"((uint32_t)(mb)), "h"((uint16_t)(mask)) : "memory")
#define TC_FENCE_AFTER()    asm volatile("tcgen05.fence::after_thread_sync;" ::: "memory")
#define TC_FENCE_BEFORE()   asm volatile("tcgen05.fence::before_thread_sync;" ::: "memory")
#define TC_WAIT_LD()        asm volatile("tcgen05.wait::ld.sync.aligned;" ::: "memory")
#define MBAR_INIT(mb, cnt)  asm volatile("mbarrier.init.shared.b64 [%0], %1;" :: "r"((uint32_t)(mb)), "r"((uint32_t)(cnt)) : "memory")
#define CLUSTER_ARRIVE()    asm volatile("barrier.cluster.arrive.aligned;" ::: "memory")
#define CLUSTER_WAIT()      asm volatile("barrier.cluster.wait.aligned;" ::: "memory")
#define MBAR_WAIT(mb, ph) do { \
    uint32_t _m = (uint32_t)(mb); uint32_t _p = (uint32_t)(ph); uint32_t _d; \
    asm volatile("{ .reg .pred p; mbarrier.try_wait.parity.acquire.cta.shared::cta.b64 p, [%1], %2; selp.b32 %0, 1, 0, p; }" \
        : "=r"(_d) : "r"(_m), "r"(_p) : "memory"); \
    if (!_d) { \
        asm volatile("{ .reg .pred P1; WL_%=: mbarrier.try_wait.parity.acquire.cta.shared::cta.b64 P1, [%0], %1, 0x989680; @P1 bra.uni WD_%=; bra.uni WL_%=; WD_%=: }" \
            :: "r"(_m), "r"(_p) : "memory"); \
    } } while(0)

static constexpr uint64_t SMEM_DESC_BASE_SW128 =
    (uint64_t(2)  << 61) | (uint64_t(1) << 46) | (uint64_t(64) << 32) | (uint64_t(1) << 16);
#define MK_DESC(a) (SMEM_DESC_BASE_SW128 | ((uint64_t)((a) >> 4) & 0x3FFF))

#define TC_LD_X32(r, t) \
    asm volatile("tcgen05.ld.sync.aligned.32x32b.x32.b32 " \
        "{%0,%1,%2,%3,%4,%5,%6,%7,%8,%9,%10,%11,%12,%13,%14,%15," \
        "%16,%17,%18,%19,%20,%21,%22,%23,%24,%25,%26,%27,%28,%29,%30,%31}, [%32];" \
        : "=r"((r)[0]),"=r"((r)[1]),"=r"((r)[2]),"=r"((r)[3]),"=r"((r)[4]),"=r"((r)[5]),"=r"((r)[6]),"=r"((r)[7]), \
          "=r"((r)[8]),"=r"((r)[9]),"=r"((r)[10]),"=r"((r)[11]),"=r"((r)[12]),"=r"((r)[13]),"=r"((r)[14]),"=r"((r)[15]), \
          "=r"((r)[16]),"=r"((r)[17]),"=r"((r)[18]),"=r"((r)[19]),"=r"((r)[20]),"=r"((r)[21]),"=r"((r)[22]),"=r"((r)[23]), \
          "=r"((r)[24]),"=r"((r)[25]),"=r"((r)[26]),"=r"((r)[27]),"=r"((r)[28]),"=r"((r)[29]),"=r"((r)[30]),"=r"((r)[31]) \
        : "r"(t))

__device__ __forceinline__ void mma_f16_ss(uint32_t d, uint64_t a, uint64_t b, uint32_t idesc, uint32_t en){
    asm volatile("{ .reg .pred p; setp.ne.u32 p, %4, 0;"
        " tcgen05.mma.cta_group::1.kind::f16 [%0], %1, %2, %3, {%5,%5,%5,%5}, p; }"
        :: "r"(d), "l"(a), "l"(b), "r"(idesc), "r"(en), "r"(0u) : "memory");
}
__device__ __forceinline__ void mma_f16_ss_cg2(uint32_t d, uint64_t a, uint64_t b, uint32_t idesc, uint32_t en){
    asm volatile("{ .reg .pred p; setp.ne.u32 p, %4, 0;"
        " tcgen05.mma.cta_group::2.kind::f16 [%0], %1, %2, %3, {%5,%5,%5,%5,%5,%5,%5,%5}, p; }"
        :: "r"(d), "l"(a), "l"(b), "r"(idesc), "r"(en), "r"(0u) : "memory");
}
#endif // HAS_TC

// ============ big fused GEMM (cg2, M=256/cluster): score_c partials ============
#define HDR_SC 4096
#define STG2 65536
#define T2_AH 0
#define T2_AL 16384
#define T2_BH 32768
#define T2_BL 49152
#define TOFF2(stg, t) (HDR_SC + (uint32_t)(stg)*STG2 + (uint32_t)(t))
#define SMEM_TC2 (HDR_SC + 2*STG2)
#define NCHUNK_SC 32

__global__ void __launch_bounds__(256, 1) __cluster_dims__(2, 1, 1)
k_tc_sc(const float* __restrict__ A,
        const __nv_bfloat16* __restrict__ Bh, const __nv_bfloat16* __restrict__ Bl,
        const float* __restrict__ bias, const float* __restrict__ state){
#if HAS_TC
    extern __shared__ char smem[];
    uint32_t sb = smem_u32(smem);
    int tid = threadIdx.x, wid = tid >> 5, lid = tid & 31;
    int rank = blockIdx.x & 1;                 // cluster along x, size 2
    int n0 = (blockIdx.x >> 1) * 256;
    int m0 = blockIdx.y * 256 + rank * 128;    // this CTA's 128 A-rows
    int b  = m0 >> 9;
    float* s_state = (float*)(smem + 64);
    float* s_bias  = (float*)(smem + 64 + 1024);

    if (wid == 0) TC_ALLOC2(sb + 0, 256);
    if (tid == 0){ MBAR_INIT(sb + 8, 1); MBAR_INIT(sb + 16, 1); }
    s_state[tid] = state[b*H + n0 + tid];
    s_bias[tid]  = bias[n0 + tid];
    __syncthreads();
    uint32_t tmem;
    asm volatile("ld.shared.b32 %0, [%1];" : "=r"(tmem) : "r"(sb));

    auto load_chunk = [&](int c, int stg){
        int k0 = c * 64;
        // A: own 128 rows x 64 fp32 -> bf16 hi/lo (SW128)
        #pragma unroll
        for (int it = 0; it < 8; it++){
            int i = tid + it*256;
            int row = i >> 4, g = i & 15;
            float4 a4 = *(const float4*)(A + (size_t)(m0+row)*KC + k0 + g*4);
            uint16_t h0,h1,h2,h3,l0,l1,l2,l3;
            split_bf16(a4.x,h0,l0); split_bf16(a4.y,h1,l1);
            split_bf16(a4.z,h2,l2); split_bf16(a4.w,h3,l3);
            uint2 hv = make_uint2((uint32_t)h0 | ((uint32_t)h1<<16), (uint32_t)h2 | ((uint32_t)h3<<16));
            uint2 lv = make_uint2((uint32_t)l0 | ((uint32_t)l1<<16), (uint32_t)l2 | ((uint32_t)l3<<16));
            uint32_t off = (uint32_t)(row*128 + g*8);
            uint32_t sw  = off ^ ((off >> 3) & 0x70);
            *(uint2*)(smem + TOFF2(stg, T2_AH) + sw) = hv;
            *(uint2*)(smem + TOFF2(stg, T2_AL) + sw) = lv;
        }
        // B split: this CTA holds N rows [n0 + rank*128, +128)
        #pragma unroll
        for (int it = 0; it < 4; it++){
            int i = tid + it*256;
            int row = i >> 3, g = i & 7;
            size_t base = ((size_t)(n0 + rank*128 + row)*KC + k0) * 2;
            uint4 h4 = *(const uint4*)((const char*)Bh + base + g*16);
            uint4 l4 = *(const uint4*)((const char*)Bl + base + g*16);
            uint32_t off = (uint32_t)(row*128 + g*16);
            uint32_t sw  = off ^ ((off >> 3) & 0x70);
            *(uint4*)(smem + TOFF2(stg, T2_BH) + sw) = h4;
            *(uint4*)(smem + TOFF2(stg, T2_BL) + sw) = l4;
        }
    };

    load_chunk(0, 0);
    asm volatile("fence.proxy.async.shared::cta;" ::: "memory");
    __syncthreads();
    CLUSTER_ARRIVE();

    // idesc cg2: F32 acc, bf16 x bf16, N=256, M_total=256
    const uint32_t idesc = (1u<<4) | (1u<<7) | (1u<<10) | (32u<<17) | (16u<<24);
    int ph[2] = {0, 0};

    for (int c = 0; c < NCHUNK_SC; c++){
        int stg = c & 1;
        CLUSTER_WAIT();                    // chunk c resident in BOTH CTAs
        if (rank == 0 && wid == 0 && elect_one()){
            uint64_t dAh = MK_DESC(sb + TOFF2(stg, T2_AH));
            uint64_t dAl = MK_DESC(sb + TOFF2(stg, T2_AL));
            uint64_t dBh = MK_DESC(sb + TOFF2(stg, T2_BH));
            uint64_t dBl = MK_DESC(sb + TOFF2(stg, T2_BL));
            #pragma unroll
            for (int ks = 0; ks < 4; ks++){
                uint64_t o = (uint64_t)(ks*2);
                mma_f16_ss_cg2(tmem, dAh + o, dBh + o, idesc, (c==0 && ks==0) ? 0u : 1u);
                mma_f16_ss_cg2(tmem, dAh + o, dBl + o, idesc, 1u);
                mma_f16_ss_cg2(tmem, dAl + o, dBh + o, idesc, 1u);
            }
            TC_COMMIT2_MC(sb + 8 + stg*8, 0x3);
        }
        if (c + 1 < NCHUNK_SC){
            int nst = stg ^ 1;
            if (c >= 1){ MBAR_WAIT(sb + 8 + nst*8, ph[nst]); ph[nst] ^= 1; }
            load_chunk(c + 1, nst);
            asm volatile("fence.proxy.async.shared::cta;" ::: "memory");
            __syncthreads();
            CLUSTER_ARRIVE();
        }
    }
    MBAR_WAIT(sb + 8 + ((NCHUNK_SC-1)&1)*8, ph[(NCHUNK_SC-1)&1]);
    TC_FENCE_AFTER();

    // epilogue: each CTA reads its own 128 D rows (256 cols fp32)
    if (wid < 4){
        float acc = 0.f;
        #pragma unroll
        for (int c0 = 0; c0 < 256; c0 += 32){
            uint32_t r[32];
            TC_LD_X32(r, tmem + c0);
            TC_WAIT_LD();
            #pragma unroll
            for (int j = 0; j < 32; j++)
                acc += tanhf(__uint_as_float(r[j]) + s_bias[c0+j]) * s_state[c0+j];
        }
        TC_FENCE_BEFORE();
        atomicAdd(&g_scorec_raw[m0 + wid*32 + lid], acc);
    }
    __syncthreads();
    if (wid == 0){ TC_RELINQ2(); TC_DEALLOC2(tmem, 256); }
    CLUSTER_ARRIVE();
    CLUSTER_WAIT();
#endif
}

// ============ generic tc GEMM: out[act][w] += W x act (cg1) ============
#define HDR_W 1024
#define WSTG 49152
#define W_AH 0
#define W_AL 16384
#define W_BH 32768
#define W_BL 40960
#define WT_OFF(stg, t) (HDR_W + (uint32_t)(stg)*WSTG + (uint32_t)(t))
#define SMEM_TW (HDR_W + 2*WSTG)

__global__ void __launch_bounds__(256, 1) k_tcW(const float* __restrict__ W,
        const __nv_bfloat16* __restrict__ act_hi, const __nv_bfloat16* __restrict__ act_lo,
        float* __restrict__ out, int Nw, int K, int kpc, int ldO){
#if HAS_TC
    extern __shared__ char smem[];
    uint32_t sb = smem_u32(smem);
    int tid = threadIdx.x, wid = tid >> 5, lid = tid & 31;
    int m0 = blockIdx.x * 128;
    int k_base = blockIdx.y * kpc * 64;

    if (wid == 0){ TC_ALLOC(sb + 0, 64); TC_RELINQ(); }
    if (tid == 0){ MBAR_INIT(sb + 8, 1); MBAR_INIT(sb + 16, 1); }
    __syncthreads();
    uint32_t tmem;
    asm volatile("ld.shared.b32 %0, [%1];" : "=r"(tmem) : "r"(sb));

    auto load_chunk = [&](int c, int stg){
        int k0 = k_base + c * 64;
        #pragma unroll
        for (int it = 0; it < 8; it++){
            int i = tid + it*256;
            int row = i >> 4, g = i & 15;
            float4 a4 = make_float4(0.f,0.f,0.f,0.f);
            if (m0 + row < Nw) a4 = *(const float4*)(W + (size_t)(m0+row)*K + k0 + g*4);
            uint16_t h0,h1,h2,h3,l0,l1,l2,l3;
            split_bf16(a4.x,h0,l0); split_bf16(a4.y,h1,l1);
            split_bf16(a4.z,h2,l2); split_bf16(a4.w,h3,l3);
            uint2 hv = make_uint2((uint32_t)h0 | ((uint32_t)h1<<16), (uint32_t)h2 | ((uint32_t)h3<<16));
            uint2 lv = make_uint2((uint32_t)l0 | ((uint32_t)l1<<16), (uint32_t)l2 | ((uint32_t)l3<<16));
            uint32_t off = (uint32_t)(row*128 + g*8);
            uint32_t sw  = off ^ ((off >> 3) & 0x70);
            *(uint2*)(smem + WT_OFF(stg, W_AH) + sw) = hv;
            *(uint2*)(smem + WT_OFF(stg, W_AL) + sw) = lv;
        }
        #pragma unroll
        for (int it = 0; it < 2; it++){
            int i = tid + it*256;
            int row = i >> 3, g = i & 7;
            size_t base = ((size_t)row*K + k0) * 2;
            uint4 h4 = *(const uint4*)((const char*)act_hi + base + g*16);
            uint4 l4 = *(const uint4*)((const char*)act_lo + base + g*16);
            uint32_t off = (uint32_t)(row*128 + g*16);
            uint32_t sw  = off ^ ((off >> 3) & 0x70);
            *(uint4*)(smem + WT_OFF(stg, W_BH) + sw) = h4;
            *(uint4*)(smem + WT_OFF(stg, W_BL) + sw) = l4;
        }
    };

    load_chunk(0, 0);
    asm volatile("fence.proxy.async.shared::cta;" ::: "memory");
    __syncthreads();

    const uint32_t idesc = (1u<<4) | (1u<<7) | (1u<<10) | (8u<<17) | (8u<<24);   // N=64, M=128
    int ph[2] = {0, 0};

    for (int c = 0; c < kpc; c++){
        int stg = c & 1;
        if (wid == 0 && elect_one()){
            uint64_t dAh = MK_DESC(sb + WT_OFF(stg, W_AH));
            uint64_t dAl = MK_DESC(sb + WT_OFF(stg, W_AL));
            uint64_t dBh = MK_DESC(sb + WT_OFF(stg, W_BH));
            uint64_t dBl = MK_DESC(sb + WT_OFF(stg, W_BL));
            #pragma unroll
            for (int ks = 0; ks < 4; ks++){
                uint64_t o = (uint64_t)(ks*2);
                mma_f16_ss(tmem, dAh + o, dBh + o, idesc, (c==0 && ks==0) ? 0u : 1u);
                mma_f16_ss(tmem, dAh + o, dBl + o, idesc, 1u);
                mma_f16_ss(tmem, dAl + o, dBh + o, idesc, 1u);
            }
            TC_COMMIT(sb + 8 + stg*8);
        }
        if (c + 1 < kpc){
            int nst = stg ^ 1;
            if (c >= 1){ MBAR_WAIT(sb + 8 + nst*8, ph[nst]); ph[nst] ^= 1; }
            load_chunk(c + 1, nst);
            asm volatile("fence.proxy.async.shared::cta;" ::: "memory");
            __syncthreads();
        }
    }
    MBAR_WAIT(sb + 8 + ((kpc-1)&1)*8, ph[(kpc-1)&1]);
    TC_FENCE_AFTER();

    if (wid < 4){
        uint32_t r0[32], r1[32];
        TC_LD_X32(r0, tmem);
        TC_LD_X32(r1, tmem + 32);
        TC_WAIT_LD();
        TC_FENCE_BEFORE();
        int m = m0 + wid*32 + lid;
        if (m < Nw){
            #pragma unroll
            for (int c = 0; c < 32; c++)
                atomicAdd(out + (size_t)c*ldO + m, __uint_as_float(r0[c]));
            #pragma unroll
            for (int c = 0; c < 32; c++)
                atomicAdd(out + (size_t)(c+32)*ldO + m, __uint_as_float(r1[c]));
        }
    }
    __syncthreads();
    if (wid == 0) TC_DEALLOC(tmem, 64);
#endif
}

// ---------------- prep kernels ----------------
__global__ void k_prep_x(const int* __restrict__ input_idx, const float* __restrict__ embed,
                         const float* __restrict__ weighted, const int* __restrict__ order,
                         int has_order){
    int b = blockIdx.x;
    int ord = has_order ? *order : 1;
    int idx = input_idx[b];
    for (int j = threadIdx.x; j < KX; j += blockDim.x){
        float v;
        if (j < E) v = embed[(size_t)idx*E + j];
        else       v = ord ? weighted[b*(2*H) + (j - E)] : 0.f;
        uint16_t h, l; split_bf16(v, h, l);
        g_x_hi[b*KX + j] = __ushort_as_bfloat16(h);
        g_x_lo[b*KX + j] = __ushort_as_bfloat16(l);
    }
}

__global__ void k_prep_state(const float* __restrict__ prev_state, const float* __restrict__ encoded,
                             const float* __restrict__ Ws_w, const float* __restrict__ Ws_b,
                             const int* __restrict__ order, int has_order){
    int i = blockIdx.x*blockDim.x + threadIdx.x;
    if (i >= B*H) return;
    int ord = has_order ? *order : 1;
    float v;
    if (ord){
        v = prev_state[i];
    } else {
        int b = i >> 10, h = i & (H-1);
        const float* e = encoded + ((size_t)b*S + (S-1))*(2*H);
        const float* w = Ws_w + (size_t)h*(2*H);
        float s = Ws_b[h];
        for (int k = 0; k < 2*H; k++) s = fmaf(e[k], w[k], s);
        v = s;
    }
    g_prev[i] = v;
    uint16_t h16, l16; split_bf16(v, h16, l16);
    g_prev_hi[i] = __ushort_as_bfloat16(h16);
    g_prev_lo[i] = __ushort_as_bfloat16(l16);
}

__global__ void k_init_gates(const float* __restrict__ bi, const float* __restrict__ bh){
    int i = blockIdx.x*blockDim.x + threadIdx.x;
    if (i < B*TH){
        int j = i % TH;
        g_gi[i] = bi[j];
        g_gh[i] = bh[j];
    }
    if (i < B*S) g_scorec_raw[i] = 0.f;
}

__global__ void k_init_scoreg(const float* __restrict__ Wg_b){
    int n = blockIdx.x*blockDim.x + threadIdx.x;
    int b = blockIdx.y;
    if (n < V) g_scoreg[(size_t)b*V + n] = Wg_b[n];
}

// ---------------- GRU combine ----------------
__global__ void k_combine(float* __restrict__ out_state){
    int i = blockIdx.x*blockDim.x + threadIdx.x;
    if (i >= B*H) return;
    int b = i >> 10, h = i & (H-1);
    const float* gi = g_gi + b*TH;
    const float* gh = g_gh + b*TH;
    float r = 1.f/(1.f + expf(-(gi[h]        + gh[h])));
    float z = 1.f/(1.f + expf(-(gi[H + h]    + gh[H + h])));
    float n = tanhf(gi[2*H + h] + r*gh[2*H + h]);
    float st = (1.f - z)*n + z*g_prev[i];
    out_state[i] = st;
    uint16_t h16, l16; split_bf16(st, h16, l16);
    g_state_hi[i] = __ushort_as_bfloat16(h16);
    g_state_lo[i] = __ushort_as_bfloat16(l16);
}

// ---------------- finalize score_c ----------------
__global__ void k_scorec_fin(const int* __restrict__ encoded_idx){
    int m = blockIdx.x*blockDim.x + threadIdx.x;
    float v = tanhf(g_scorec_raw[m]);
    if (encoded_idx[m] == 0) v -= 1000.f;
    g_scorec[m] = v;
}

// ---------------- softmax stats / writeout / tail ----------------
__global__ void k_rowstats(){
    int b = blockIdx.x;
    __shared__ float red[256];
    const float* sg = g_scoreg + (size_t)b*V;
    const float* sc = g_scorec + b*S;
    float mx = -1e30f;
    for (int i = threadIdx.x; i < V; i += 256) mx = fmaxf(mx, sg[i]);
    for (int i = threadIdx.x; i < S; i += 256) mx = fmaxf(mx, sc[i]);
    red[threadIdx.x] = mx; __syncthreads();
    for (int st = 128; st; st >>= 1){
        if (threadIdx.x < st) red[threadIdx.x] = fmaxf(red[threadIdx.x], red[threadIdx.x+st]);
        __syncthreads();
    }
    mx = red[0];
    __syncthreads();
    float sm = 0.f;
    for (int i = threadIdx.x; i < V; i += 256) sm += expf(sg[i] - mx);
    for (int i = threadIdx.x; i < S; i += 256) sm += expf(sc[i] - mx);
    red[threadIdx.x] = sm; __syncthreads();
    for (int st = 128; st; st >>= 1){
        if (threadIdx.x < st) red[threadIdx.x] += red[threadIdx.x+st];
        __syncthreads();
    }
    if (threadIdx.x == 0){ g_rowmax[b] = mx; g_rowsum[b] = red[0]; }
}

__global__ void k_writeout(float* __restrict__ out){
    long long i = (long long)blockIdx.x*256 + threadIdx.x;
    if (i >= (long long)B*OUTW) return;
    int b = (int)(i / OUTW);
    int c = (int)(i - (long long)b*OUTW);
    float v;
    if (c < V) v = expf(g_scoreg[(size_t)b*V + c] - g_rowmax[b]) / g_rowsum[b];
    else       v = 1e-4f;
    out[i] = v;
}

__global__ void k_tail(float* __restrict__ out, float* __restrict__ out_w,
                       const int* __restrict__ encoded_idx, const int* __restrict__ input_idx,
                       const float* __restrict__ encoded){
    int b = blockIdx.x;
    __shared__ float pc[S];
    __shared__ float attn[S];
    __shared__ int   icnt[256];
    float mx  = g_rowmax[b];
    float inv = 1.f / g_rowsum[b];
    int target = input_idx[b];
    int c = 0;
    for (int s = threadIdx.x; s < S; s += 256){
        float p = expf(g_scorec[b*S + s] - mx) * inv;
        pc[s] = p;
        if (encoded_idx[b*S + s] == target) c++;
    }
    icnt[threadIdx.x] = c; __syncthreads();
    for (int st = 128; st; st >>= 1){
        if (threadIdx.x < st) icnt[threadIdx.x] += icnt[threadIdx.x+st];
        __syncthreads();
    }
    int ssum = icnt[0];
    float scale = (ssum > 1) ? 1.f/(float)ssum : 1.f;
    for (int s = threadIdx.x; s < S; s += 256){
        int idx = encoded_idx[b*S + s];
        atomicAdd(&out[(size_t)b*OUTW + idx], pc[s]);
        attn[s] = (idx == target) ? pc[s]*scale : 0.f;
    }
    __syncthreads();
    float acc[8] = {0.f,0.f,0.f,0.f,0.f,0.f,0.f,0.f};
    const float* eb = encoded + (size_t)b*S*(2*H);
    for (int s = 0; s < S; s++){
        float a = attn[s];
        if (a != 0.f){
            const float* er = eb + (size_t)s*(2*H);
            #pragma unroll
            for (int j = 0; j < 8; j++)
                acc[j] = fmaf(a, er[threadIdx.x + j*256], acc[j]);
        }
    }
    #pragma unroll
    for (int j = 0; j < 8; j++)
        out_w[b*(2*H) + threadIdx.x + j*256] = acc[j];
}

// ---------------- launch ----------------
extern "C" void kernel_launch(void* const* d_in, const int* in_sizes, int n_in,
                              void* d_out, int out_size){
    const int*   input_idx   = (const int*)  d_in[0];
    const float* encoded     = (const float*)d_in[1];
    const int*   encoded_idx = (const int*)  d_in[2];
    const float* prev_state  = (const float*)d_in[3];
    const float* weighted    = (const float*)d_in[4];
    int off = 0;
    const int* order = nullptr;
    if (n_in >= 17 && in_sizes[5] == 1){ order = (const int*)d_in[5]; off = 1; }
    const float* embed  = (const float*)d_in[5+off];
    const float* gru_wi = (const float*)d_in[6+off];
    const float* gru_wh = (const float*)d_in[7+off];
    const float* gru_bi = (const float*)d_in[8+off];
    const float* gru_bh = (const float*)d_in[9+off];
    const float* Ws_w   = (const float*)d_in[10+off];
    const float* Ws_b   = (const float*)d_in[11+off];
    const float* Wg_w   = (const float*)d_in[12+off];
    const float* Wg_b   = (const float*)d_in[13+off];
    const float* Wc_w   = (const float*)d_in[14+off];
    const float* Wc_b   = (const float*)d_in[15+off];
    int has_order = (order != nullptr);
    if (!order) order = input_idx;

    float* out       = (float*)d_out;
    float* out_state = out + (size_t)B*OUTW;
    float* out_w     = out_state + (size_t)B*H;

    static float *p_gi = nullptr, *p_gh, *p_scoreg;
    static __nv_bfloat16 *p_Bh, *p_Bl, *p_xh, *p_xl, *p_ph, *p_pl, *p_sh, *p_sl;
    if (!p_gi){
        cudaGetSymbolAddress((void**)&p_gi,     g_gi);
        cudaGetSymbolAddress((void**)&p_gh,     g_gh);
        cudaGetSymbolAddress((void**)&p_scoreg, g_scoreg);
        cudaGetSymbolAddress((void**)&p_Bh,     g_Wc_hi);
        cudaGetSymbolAddress((void**)&p_Bl,     g_Wc_lo);
        cudaGetSymbolAddress((void**)&p_xh,     g_x_hi);
        cudaGetSymbolAddress((void**)&p_xl,     g_x_lo);
        cudaGetSymbolAddress((void**)&p_ph,     g_prev_hi);
        cudaGetSymbolAddress((void**)&p_pl,     g_prev_lo);
        cudaGetSymbolAddress((void**)&p_sh,     g_state_hi);
        cudaGetSymbolAddress((void**)&p_sl,     g_state_lo);
        cudaFuncSetAttribute(k_tc_sc, cudaFuncAttributeMaxDynamicSharedMemorySize, SMEM_TC2);
        cudaFuncSetAttribute(k_tcW,   cudaFuncAttributeMaxDynamicSharedMemorySize, SMEM_TW);
    }

    k_prep_x    <<<B, 256>>>(input_idx, embed, weighted, order, has_order);
    k_prep_state<<<(B*H)/256, 256>>>(prev_state, encoded, Ws_w, Ws_b, order, has_order);
    k_init_gates<<<(B*TH + 255)/256, 256>>>(gru_bi, gru_bh);
    k_convB     <<<(H*KC)/1024, 256>>>(Wc_w);

    // GRU gate GEMMs (deeper split-K for occupancy)
    k_tcW<<<dim3(TH/128, 5), 256, SMEM_TW>>>(gru_wi, p_xh, p_xl, p_gi, TH, KX, 8, TH);
    k_tcW<<<dim3(TH/128, 4), 256, SMEM_TW>>>(gru_wh, p_ph, p_pl, p_gh, TH, H,  4, TH);
    k_combine<<<(B*H)/256, 256>>>(out_state);

    // score_g = state @ Wg^T + b
    k_init_scoreg<<<dim3((V+255)/256, B), 256>>>(Wg_b);
    k_tcW<<<dim3((V+127)/128, 1), 256, SMEM_TW>>>(Wg_w, p_sh, p_sl, p_scoreg, V, H, H/64, V);

    // fused big GEMM (cg2) + score_c partials
    k_tc_sc<<<dim3(8, MS/256), 256, SMEM_TC2>>>(encoded, p_Bh, p_Bl, Wc_b, out_state);
    k_scorec_fin<<<MS/256, 256>>>(encoded_idx);

    k_rowstats<<<B, 256>>>();
    k_writeout<<<((long long)B*OUTW + 255)/256, 256>>>(out);
    k_tail    <<<B, 256>>>(out, out_w, encoded_idx, input_idx, encoded);
}